// round 11
// baseline (speedup 1.0000x reference)
#include <cuda_runtime.h>
#include <math.h>
#include <stdint.h>

#define N_NODES 6000
#define DEG 16
#define N_EDGES 96000
#define D_MODEL 256
#define D_MSG 64
#define D_FF 1024
#define N_LAYERS 3
#define RBF_BINS 256
#define WIN 32
#define N_SPEC 108

// ---------------- scratch (static device memory; no allocation) ----------------
__device__ float g_xj[N_NODES * D_MSG];
__device__ float g_xi[N_NODES * D_MSG];
__device__ float g_xjsplit[4 * N_NODES * D_MSG];
__device__ float g_xn[N_NODES * D_MSG];
__device__ float g_h[N_NODES * D_FF];
__device__ float g_w2t[2 * D_FF * D_MODEL];
__device__ float g_wc[4 * D_MSG * D_FF];
__device__ float g_embsrc[112 * D_MSG];
__device__ float g_embdst[112 * D_MSG];
__device__ float g_bx[4 * D_MSG];
__device__ float g_hpart[60 * D_FF];
__device__ float g_hsum[D_FF];
__device__ float g_wfc2[D_FF];
__device__ float g_zeros[D_FF];

// ---------------- packed f32x2 helpers (sm_10x) ----------------
__device__ __forceinline__ uint64_t pk2(float lo, float hi) {
    uint64_t r;
    asm("mov.b64 %0, {%1, %2};" : "=l"(r) : "f"(lo), "f"(hi));
    return r;
}
__device__ __forceinline__ void upk2(float& lo, float& hi, uint64_t v) {
    asm("mov.b64 {%0, %1}, %2;" : "=f"(lo), "=f"(hi) : "l"(v));
}
__device__ __forceinline__ void ffma2(uint64_t& d, uint64_t a, uint64_t b) {
    asm("fma.rn.f32x2 %0, %1, %2, %0;" : "+l"(d) : "l"(a), "l"(b));
}

// ---------------- transpose [R,C] -> [C,R], z selects layer ----------------
__global__ void transpose_kernel(const float* __restrict__ in,
                                 float* __restrict__ out, int R, int C) {
    __shared__ float tile[32][33];
    in += (size_t)blockIdx.z * R * C;
    out += (size_t)blockIdx.z * R * C;
    int c0 = blockIdx.x * 32, r0 = blockIdx.y * 32;
    int tx = threadIdx.x, ty = threadIdx.y;
#pragma unroll
    for (int i = 0; i < 4; i++)
        tile[ty + i * 8][tx] = in[(size_t)(r0 + ty + i * 8) * C + c0 + tx];
    __syncthreads();
#pragma unroll
    for (int i = 0; i < 4; i++)
        out[(size_t)(c0 + ty + i * 8) * R + r0 + tx] = tile[tx][ty + i * 8];
}

// ---------------- species projections: es/ed = emb @ W0^T + b (108 blocks) ----
__global__ void species_kernel(const float* __restrict__ emb,
                               const float* __restrict__ Wsrc,
                               const float* __restrict__ bsrc,
                               const float* __restrict__ Wdst,
                               const float* __restrict__ bdst,
                               float* __restrict__ es,
                               float* __restrict__ ed) {
    __shared__ float se[256];
    int s = blockIdx.x;
    int t = threadIdx.x;
    se[t] = emb[s * 256 + t];
    se[t + 128] = emb[s * 256 + t + 128];
    __syncthreads();
    int c = t & 63;
    bool isdst = t >= 64;
    const float* W = (isdst ? Wdst : Wsrc) + c * 256;
    float acc = isdst ? bdst[c] : bsrc[c];
#pragma unroll 16
    for (int k = 0; k < 256; k += 4) {
        float4 w = *(const float4*)(W + k);
        acc = fmaf(se[k + 0], w.x, acc);
        acc = fmaf(se[k + 1], w.y, acc);
        acc = fmaf(se[k + 2], w.z, acc);
        acc = fmaf(se[k + 3], w.w, acc);
    }
    (isdst ? ed : es)[s * 64 + c] = acc;
}

// ---------------- fused bias ----------------
__global__ void biasfold_kernel(const float* __restrict__ Wsrc,
                                const float* __restrict__ Wdst,
                                const float* __restrict__ bsrc,
                                const float* __restrict__ bdst,
                                const float* __restrict__ b2,
                                float* __restrict__ bx) {
    int which = blockIdx.x;
    int l = 1 + (which >> 1);
    bool isdst = which & 1;
    const float* W = (isdst ? Wdst : Wsrc) + (size_t)l * D_MSG * D_MODEL;
    const float* bb = (isdst ? bdst : bsrc) + (size_t)l * D_MSG;
    const float* b2p = b2 + (size_t)(l - 1) * D_MODEL;
    int c = threadIdx.x;
    float acc = bb[c];
    for (int k = 0; k < D_MODEL; k++) acc = fmaf(W[c * D_MODEL + k], b2p[k], acc);
    bx[which * D_MSG + c] = acc;
}

// ---------------- layer-0 projection gather ----------------
__global__ void gather_kernel(const int* __restrict__ an,
                              const float* __restrict__ es,
                              const float* __restrict__ ed,
                              float* __restrict__ xj,
                              float* __restrict__ xi) {
    int i = blockIdx.x;
    int c = threadIdx.x;
    int a = an[i];
    xj[i * D_MSG + c] = es[a * D_MSG + c];
    xi[i * D_MSG + c] = ed[a * D_MSG + c];
}

// ---------------- merged edge + triplet kernel ---------------------------------
// Per node group: windowed-RBF edge features (straight into smem, never global),
// rhat inline, then triplet attention -> xn. xij never touches global memory.
#define EDGE_WPITCH 68
#define ET_SMEM_FLOATS (256 * EDGE_WPITCH + 64 * 17 + 16 * WIN + 48 + 64 + 256 + 16 * 4 + 32)
#define ET_SMEM_BYTES (ET_SMEM_FLOATS * 4)

__global__ void edge_triplet_kernel(const float* __restrict__ r,
                                    const int* __restrict__ src,
                                    const float* __restrict__ We,
                                    const float* __restrict__ bedge,
                                    const float* __restrict__ attn,
                                    const float* __restrict__ xj,
                                    const float* __restrict__ xi,
                                    float* __restrict__ xn) {
    extern __shared__ float sm[];
    float* sWt = sm;                           // [256][68]
    float* sx  = sm + 256 * EDGE_WPITCH;       // [64][17]  xij^T
    float* sy  = sx + 64 * 17;                 // [16][WIN]
    float* rh  = sy + 16 * WIN;                // [16][3]
    float* sat = rh + 48;                      // [64]
    float* sl  = sat + 64;                     // [16][16]
    float* mq  = sl + 256;                     // [16]
    float* zi  = mq + 16;
    float* wp  = zi + 16;
    float* sd  = wp + 16;
    int* sb0   = (int*)(sd + 16);
    int* ssrc  = sb0 + 16;

    int t = threadIdx.x;
    for (int idx = t; idx < 64 * 256; idx += 256) {
        int ch = idx >> 8, b = idx & 255;
        sWt[b * EDGE_WPITCH + ch] = We[idx];
    }
    if (t < 64) sat[t] = attn[t];
    int e_sub = t >> 4;
    int chv = t & 15;
    float4 bed = *(const float4*)&bedge[chv * 4];
    const float inv_step = 255.0f / 8.0f;
    const float step = 8.0f / 255.0f;
    const float gamma = inv_step;

    for (int g = blockIdx.x; g < N_NODES; g += gridDim.x) {
        __syncthreads();
        if (t < 16) {
            int e = g * 16 + t;
            float rx = r[e * 3 + 0], ry = r[e * 3 + 1], rz = r[e * 3 + 2];
            float d = sqrtf(rx * rx + ry * ry + rz * rz);
            float inv = 1.0f / d;
            rh[t * 3 + 0] = rx * inv;
            rh[t * 3 + 1] = ry * inv;
            rh[t * 3 + 2] = rz * inv;
            int cb = (int)(d * inv_step + 0.5f);
            int b0 = cb - WIN / 2;
            b0 = b0 < 0 ? 0 : (b0 > 256 - WIN ? 256 - WIN : b0);
            sb0[t] = b0;
            sd[t] = d;
            ssrc[t] = src[e];
        }
        __syncthreads();
        {   // Gaussian window, 2 bins/thread
            float d = sd[e_sub];
            int b0 = sb0[e_sub];
            int jb = chv * 2;
#pragma unroll
            for (int i = 0; i < 2; i++) {
                float tt = d - (float)(b0 + jb + i) * step;
                sy[e_sub * WIN + jb + i] = __expf(-gamma * tt * tt);
            }
        }
        __syncthreads();
        {   // windowed dot (f32x2 channel pairs) + gathers -> sx[ch][e]
            int b0 = sb0[e_sub];
            const float* wptr = sWt + (size_t)b0 * EDGE_WPITCH + chv * 4;
            const float* yp = sy + e_sub * WIN;
            uint64_t a0 = pk2(bed.x, bed.y);
            uint64_t a1 = pk2(bed.z, bed.w);
#pragma unroll 16
            for (int j = 0; j < WIN; j++) {
                float yv = yp[j];
                uint64_t yd = pk2(yv, yv);
                float4 w = *(const float4*)(wptr + (size_t)j * EDGE_WPITCH);
                ffma2(a0, yd, pk2(w.x, w.y));
                ffma2(a1, yd, pk2(w.z, w.w));
            }
            int sidx = ssrc[e_sub];
            float4 aj = *(const float4*)&xj[sidx * 64 + chv * 4];
            float4 ai = *(const float4*)&xi[g * 64 + chv * 4];
            float o0, o1, o2, o3;
            upk2(o0, o1, a0);
            upk2(o2, o3, a1);
            int ch = chv * 4;
            sx[(ch + 0) * 17 + e_sub] = o0 + aj.x + ai.x;
            sx[(ch + 1) * 17 + e_sub] = o1 + aj.y + ai.y;
            sx[(ch + 2) * 17 + e_sub] = o2 + aj.z + ai.z;
            sx[(ch + 3) * 17 + e_sub] = o3 + aj.w + ai.w;
        }
        __syncthreads();
        // triplet attention: 120 unordered pairs (symmetric logits)
        if (t < 120) {
            int q = (int)((1.0f + sqrtf(8.0f * (float)t + 1.0f)) * 0.5f);
            if (q * (q - 1) / 2 > t) q--;
            else if (q * (q + 1) / 2 <= t) q++;
            int p = t - q * (q - 1) / 2;

            float c = rh[p * 3 + 0] * rh[q * 3 + 0] +
                      rh[p * 3 + 1] * rh[q * 3 + 1] +
                      rh[p * 3 + 2] * rh[q * 3 + 2];
            c = fminf(fmaxf(c, -1.0f + 1e-6f), 1.0f - 1e-6f);
            float c2 = 2.0f * c;
            float t0 = 1.0f, t1 = c;
            float acc;
            {
                float s = 1.0f + sx[0 * 17 + p] + sx[0 * 17 + q];
                float si = __fdividef(s, 1.0f + __expf(-s));
                acc = sat[0] * si;
            }
#pragma unroll
            for (int k = 1; k < 64; k++) {
                float z = t1;
                float s = z + sx[k * 17 + p] + sx[k * 17 + q];
                float si = __fdividef(s, 1.0f + __expf(-s));
                acc = fmaf(sat[k], si, acc);
                float tn = fmaf(c2, t1, -t0);
                t0 = t1; t1 = tn;
            }
            sl[q * 16 + p] = acc;
            sl[p * 16 + q - 1] = acc;
        }
        __syncthreads();
        if (t < 16) {
            int q = t;
            float m = -1e30f;
#pragma unroll
            for (int ps = 0; ps < 15; ps++) m = fmaxf(m, sl[q * 16 + ps]);
            float z = 0.0f;
#pragma unroll
            for (int ps = 0; ps < 15; ps++) z += __expf(sl[q * 16 + ps] - m);
            mq[q] = m;
            zi[q] = __fdividef(1.0f, z);
        }
        __syncthreads();
        if (t < 16) {
            int p = t;
            float w = 0.0f;
#pragma unroll
            for (int q = 0; q < 16; q++) {
                if (q == p) continue;
                int ps = (p < q) ? p : p - 1;
                w += __expf(sl[q * 16 + ps] - mq[q]) * zi[q];
            }
            wp[p] = w;
        }
        __syncthreads();
        if (t < 64) {
            float acc = 0.0f;
#pragma unroll
            for (int p = 0; p < 16; p++) acc = fmaf(wp[p], sx[t * 17 + p], acc);
            xn[g * 64 + t] = acc;
        }
    }
}

// ---------------- SGEMM: C[M,N] = A[M,K] @ B[N,K]^T + bias ---------------------
// 128 threads, 64x64 tile, f32x2 row-pairs. lda/ldb row strides.
// EPI 1: silu(+bias)
// EPI 4: fused dual projection with K-split: grid (2, MB, 2);
//        x selects src/dst weight+bias, z selects K-half; C -> 4 partials
// EPI 5: dual-A precompute (blockIdx.y selects A/C; m0=0, zero bias)
template <int EPI>
__global__ __launch_bounds__(128)
void gemm64(const float* __restrict__ A,
            const float* __restrict__ B,
            float* __restrict__ C,
            int M, int N, int K, int lda, int ldb,
            const float* __restrict__ bias,
            const float* __restrict__ B2,
            const float* __restrict__ bias2,
            float* __restrict__ C2) {
    __shared__ float As[32][64];
    __shared__ float Bs[32][64];
    int t = threadIdx.x;
    int n0 = blockIdx.x * 64;
    int m0 = blockIdx.y * 64;
    if (EPI == 4) {
        int z = blockIdx.z;
        int wsel = blockIdx.x;
        B = B + (size_t)wsel * 64 * 1024 + z * 512;
        bias = (z == 0) ? (bias + wsel * 64) : bias2;
        C = C + (size_t)(z * 2 + wsel) * (N_NODES * 64);
        A = A + z * 512;
        n0 = 0;
    }
    if (EPI == 5) {
        m0 = 0;
        if (blockIdx.y == 1) { A = B2; C = C2; }
    }
    int r = t & 63;
    int kb = (t >> 6) * 16;
    int rg8 = (t >> 4) * 8;
    int cg4 = (t & 15) * 4;

    uint64_t acc2[4][4];
#pragma unroll
    for (int i = 0; i < 4; i++)
#pragma unroll
        for (int j = 0; j < 4; j++) acc2[i][j] = 0ull;

    int rowA = m0 + r;
    bool okA = rowA < M;
    const float* Ap = A + (size_t)(okA ? rowA : (M - 1)) * lda + kb;
    const float* Bp = B + (size_t)(n0 + r) * ldb + kb;

    for (int k0 = 0; k0 < K; k0 += 32) {
        float4 av[4], bv[4];
#pragma unroll
        for (int i = 0; i < 4; i++) {
            av[i] = okA ? *(const float4*)(Ap + k0 + i * 4)
                        : make_float4(0.f, 0.f, 0.f, 0.f);
            bv[i] = *(const float4*)(Bp + k0 + i * 4);
        }
        __syncthreads();
#pragma unroll
        for (int i = 0; i < 4; i++) {
            As[kb + i * 4 + 0][r] = av[i].x;
            As[kb + i * 4 + 1][r] = av[i].y;
            As[kb + i * 4 + 2][r] = av[i].z;
            As[kb + i * 4 + 3][r] = av[i].w;
            Bs[kb + i * 4 + 0][r] = bv[i].x;
            Bs[kb + i * 4 + 1][r] = bv[i].y;
            Bs[kb + i * 4 + 2][r] = bv[i].z;
            Bs[kb + i * 4 + 3][r] = bv[i].w;
        }
        __syncthreads();
#pragma unroll 8
        for (int kk = 0; kk < 32; kk++) {
            float4 a0 = *(const float4*)&As[kk][rg8];
            float4 a1 = *(const float4*)&As[kk][rg8 + 4];
            float4 b = *(const float4*)&Bs[kk][cg4];
            uint64_t ap[4] = {pk2(a0.x, a0.y), pk2(a0.z, a0.w),
                              pk2(a1.x, a1.y), pk2(a1.z, a1.w)};
            uint64_t bd[4] = {pk2(b.x, b.x), pk2(b.y, b.y),
                              pk2(b.z, b.z), pk2(b.w, b.w)};
#pragma unroll
            for (int i = 0; i < 4; i++)
#pragma unroll
                for (int j = 0; j < 4; j++)
                    ffma2(acc2[i][j], ap[i], bd[j]);
        }
    }
    __syncthreads();

    float4 b4 = *(const float4*)&bias[n0 + cg4];
    float bb[4] = {b4.x, b4.y, b4.z, b4.w};
#pragma unroll
    for (int i = 0; i < 4; i++) {
        float v0[4], v1[4];
#pragma unroll
        for (int j = 0; j < 4; j++) {
            float lo, hi;
            upk2(lo, hi, acc2[i][j]);
            lo += bb[j];
            hi += bb[j];
            if (EPI == 1) {
                lo = __fdividef(lo, 1.0f + __expf(-lo));
                hi = __fdividef(hi, 1.0f + __expf(-hi));
            }
            v0[j] = lo;
            v1[j] = hi;
        }
        int m = m0 + rg8 + 2 * i;
        if (m < M)
            *(float4*)&C[(size_t)m * N + n0 + cg4] =
                make_float4(v0[0], v0[1], v0[2], v0[3]);
        if (m + 1 < M)
            *(float4*)&C[(size_t)(m + 1) * N + n0 + cg4] =
                make_float4(v1[0], v1[1], v1[2], v1[3]);
    }
}

// ---------------- combine K-split projection partials ----------------
__global__ void projadd_kernel(const float* __restrict__ sp,
                               float* __restrict__ xj,
                               float* __restrict__ xi) {
    int i = blockIdx.x * 256 + threadIdx.x;   // over N_NODES*64/4 float4s
    if (i < N_NODES * 16) {
        const float4* s0 = (const float4*)sp;
        float4 a = s0[i];
        float4 b = s0[2 * N_NODES * 16 + i];
        ((float4*)xj)[i] = make_float4(a.x + b.x, a.y + b.y, a.z + b.z, a.w + b.w);
        float4 c = s0[N_NODES * 16 + i];
        float4 d = s0[3 * N_NODES * 16 + i];
        ((float4*)xi)[i] = make_float4(c.x + d.x, c.y + d.y, c.z + d.z, c.w + d.w);
    }
}

// ---------------- head ----------------
__global__ void colsum1_kernel(const float* __restrict__ h,
                               float* __restrict__ hpart) {
    int f = blockIdx.y * 256 + threadIdx.x;
    int n0 = blockIdx.x * 100;
    float acc = 0.0f;
    for (int n = n0; n < n0 + 100; n++) acc += h[(size_t)n * D_FF + f];
    hpart[blockIdx.x * D_FF + f] = acc;
}

__global__ void colsum2_kernel(const float* __restrict__ hpart,
                               float* __restrict__ hsum) {
    int f = blockIdx.x * 256 + threadIdx.x;
    float acc = 0.0f;
    for (int b = 0; b < 60; b++) acc += hpart[b * D_FF + f];
    hsum[f] = acc;
}

__global__ void wfc2_kernel(const float* __restrict__ W2l2,
                            const float* __restrict__ Wfc,
                            float* __restrict__ wfc2) {
    int f = blockIdx.x * 256 + threadIdx.x;
    float acc = 0.0f;
    for (int k = 0; k < D_MODEL; k++)
        acc = fmaf(W2l2[(size_t)k * D_FF + f], Wfc[k], acc);
    wfc2[f] = acc;
}

__global__ void final_kernel(const float* __restrict__ hsum,
                             const float* __restrict__ wfc2,
                             const float* __restrict__ b2l2,
                             const float* __restrict__ Wfc,
                             const float* __restrict__ bfc,
                             float* __restrict__ out) {
    __shared__ float red[256];
    int t = threadIdx.x;
    float acc = 0.0f;
    for (int f = t; f < D_FF; f += 256) acc = fmaf(hsum[f], wfc2[f], acc);
    acc *= (1.0f / (float)N_NODES);
    acc = fmaf(b2l2[t], Wfc[t], acc);
    red[t] = acc;
    __syncthreads();
    for (int s = 128; s > 0; s >>= 1) {
        if (t < s) red[t] += red[t + s];
        __syncthreads();
    }
    if (t == 0) out[0] = red[0] + bfc[0];
}

// ---------------- launcher ----------------
extern "C" void kernel_launch(void* const* d_in, const int* in_sizes, int n_in,
                              void* d_out, int out_size) {
    const float* r     = (const float*)d_in[0];
    const int*   an    = (const int*)d_in[1];
    const int*   src   = (const int*)d_in[2];
    const float* emb   = (const float*)d_in[6];
    const float* Wsrc  = (const float*)d_in[7];
    const float* bsrc  = (const float*)d_in[8];
    const float* Wdst  = (const float*)d_in[9];
    const float* bdst  = (const float*)d_in[10];
    const float* Wedge = (const float*)d_in[11];
    const float* bedge = (const float*)d_in[12];
    const float* attn  = (const float*)d_in[13];
    const float* W1    = (const float*)d_in[14];
    const float* b1    = (const float*)d_in[15];
    const float* W2    = (const float*)d_in[16];
    const float* b2    = (const float*)d_in[17];
    const float* Wfc   = (const float*)d_in[18];
    const float* bfc   = (const float*)d_in[19];
    float* out = (float*)d_out;

    float *xj, *xi, *xjsplit, *xn, *h, *w2t, *wc, *es, *ed, *bx;
    float *hpart, *hsum, *wfc2, *zeros;
    cudaGetSymbolAddress((void**)&xj,   g_xj);
    cudaGetSymbolAddress((void**)&xi,   g_xi);
    cudaGetSymbolAddress((void**)&xjsplit, g_xjsplit);
    cudaGetSymbolAddress((void**)&xn,   g_xn);
    cudaGetSymbolAddress((void**)&h,    g_h);
    cudaGetSymbolAddress((void**)&w2t,  g_w2t);
    cudaGetSymbolAddress((void**)&wc,   g_wc);
    cudaGetSymbolAddress((void**)&es,   g_embsrc);
    cudaGetSymbolAddress((void**)&ed,   g_embdst);
    cudaGetSymbolAddress((void**)&bx,   g_bx);
    cudaGetSymbolAddress((void**)&hpart, g_hpart);
    cudaGetSymbolAddress((void**)&hsum, g_hsum);
    cudaGetSymbolAddress((void**)&wfc2, g_wfc2);
    cudaGetSymbolAddress((void**)&zeros, g_zeros);

    cudaFuncSetAttribute(edge_triplet_kernel,
                         cudaFuncAttributeMaxDynamicSharedMemorySize,
                         ET_SMEM_BYTES);

    // ---------- precompute ----------
    transpose_kernel<<<dim3(32, 8, 2), dim3(32, 8)>>>(W2, w2t, D_MODEL, D_FF);
    species_kernel<<<N_SPEC, 128>>>(emb, Wsrc, bsrc, Wdst, bdst, es, ed);
    gemm64<5><<<dim3(16, 2), 128>>>(
        Wsrc + 1 * 64 * 256, w2t, wc + 0 * 64 * D_FF, 64, D_FF, 256, 256, 256,
        zeros, Wdst + 1 * 64 * 256, nullptr, wc + 1 * 64 * D_FF);
    gemm64<5><<<dim3(16, 2), 128>>>(
        Wsrc + 2 * 64 * 256, w2t + D_FF * D_MODEL, wc + 2 * 64 * D_FF,
        64, D_FF, 256, 256, 256,
        zeros, Wdst + 2 * 64 * 256, nullptr, wc + 3 * 64 * D_FF);
    biasfold_kernel<<<4, 64>>>(Wsrc, Wdst, bsrc, bdst, b2, bx);
    gather_kernel<<<N_NODES, 64>>>(an, es, ed, xj, xi);

    const int MB_NODE = (N_NODES + 63) / 64;   // 94

    // ---------- layers ----------
    for (int l = 0; l < N_LAYERS; l++) {
        edge_triplet_kernel<<<296, 256, ET_SMEM_BYTES>>>(
            r, src, Wedge + l * 64 * 256, bedge + l * 64, attn + l * 64,
            xj, xi, xn);
        gemm64<1><<<dim3(16, MB_NODE), 128>>>(
            xn, W1 + l * D_FF * 64, h, N_NODES, D_FF, 64, 64, 64,
            b1 + l * D_FF, nullptr, nullptr, nullptr);
        if (l < 2) {
            gemm64<4><<<dim3(2, MB_NODE, 2), 128>>>(
                h, wc + (size_t)(2 * l) * 64 * D_FF, xjsplit,
                N_NODES, 64, 512, 1024, 1024,
                bx + 2 * l * 64, nullptr, zeros, nullptr);
            projadd_kernel<<<(N_NODES * 16 + 255) / 256, 256>>>(xjsplit, xj, xi);
        }
    }

    // ---------- head ----------
    colsum1_kernel<<<dim3(60, 4), 256>>>(h, hpart);
    colsum2_kernel<<<4, 256>>>(hpart, hsum);
    wfc2_kernel<<<4, 256>>>(W2 + 2 * D_MODEL * D_FF, Wfc, wfc2);
    final_kernel<<<1, 256>>>(hsum, wfc2, b2 + 2 * D_MODEL, Wfc, bfc, out);
}

// round 12
// speedup vs baseline: 1.0103x; 1.0103x over previous
#include <cuda_runtime.h>
#include <math.h>
#include <stdint.h>

#define N_NODES 6000
#define DEG 16
#define N_EDGES 96000
#define D_MODEL 256
#define D_MSG 64
#define D_FF 1024
#define N_LAYERS 3
#define RBF_BINS 256
#define WIN 32
#define N_SPEC 108

// ---------------- scratch (static device memory; no allocation) ----------------
__device__ float g_xj[N_NODES * D_MSG];
__device__ float g_xi[N_NODES * D_MSG];
__device__ float g_xn[N_NODES * D_MSG];
__device__ float g_h[N_NODES * D_FF];
__device__ float g_wc[4 * D_MSG * D_FF];
__device__ float g_embsrc[112 * D_MSG];
__device__ float g_embdst[112 * D_MSG];
__device__ float g_bx[4 * D_MSG];
__device__ float g_hpart[60 * D_FF];
__device__ float g_hsum[D_FF];
__device__ float g_wfc2[D_FF];

// ---------------- packed f32x2 helpers (sm_10x) ----------------
__device__ __forceinline__ uint64_t pk2(float lo, float hi) {
    uint64_t r;
    asm("mov.b64 %0, {%1, %2};" : "=l"(r) : "f"(lo), "f"(hi));
    return r;
}
__device__ __forceinline__ void upk2(float& lo, float& hi, uint64_t v) {
    asm("mov.b64 {%0, %1}, %2;" : "=f"(lo), "=f"(hi) : "l"(v));
}
__device__ __forceinline__ void ffma2(uint64_t& d, uint64_t a, uint64_t b) {
    asm("fma.rn.f32x2 %0, %1, %2, %0;" : "+l"(d) : "l"(a), "l"(b));
}

// ---------------- species projections: es/ed = emb @ W0^T + b ----------------
__global__ void species_kernel(const float* __restrict__ emb,
                               const float* __restrict__ Wsrc,
                               const float* __restrict__ bsrc,
                               const float* __restrict__ Wdst,
                               const float* __restrict__ bdst,
                               float* __restrict__ es,
                               float* __restrict__ ed) {
    __shared__ float se[256];
    int s = blockIdx.x;
    int t = threadIdx.x;
    se[t] = emb[s * 256 + t];
    se[t + 128] = emb[s * 256 + t + 128];
    __syncthreads();
    int c = t & 63;
    bool isdst = t >= 64;
    const float* W = (isdst ? Wdst : Wsrc) + c * 256;
    float acc = isdst ? bdst[c] : bsrc[c];
#pragma unroll 16
    for (int k = 0; k < 256; k += 4) {
        float4 w = *(const float4*)(W + k);
        acc = fmaf(se[k + 0], w.x, acc);
        acc = fmaf(se[k + 1], w.y, acc);
        acc = fmaf(se[k + 2], w.z, acc);
        acc = fmaf(se[k + 3], w.w, acc);
    }
    (isdst ? ed : es)[s * 64 + c] = acc;
}

// ---------------- fused weight precompute: wc[s] = W[s] @ W2[l(s)] ------------
// s: 0=src L1, 1=dst L1, 2=src L2, 3=dst L2. No transpose of W2 needed.
// grid (8 f-tiles, 4 s), 256 threads; per thread 8c x 4f outputs.
__global__ void wc_kernel(const float* __restrict__ Wsrc,
                          const float* __restrict__ Wdst,
                          const float* __restrict__ W2,
                          float* __restrict__ wc) {
    __shared__ float sW[64 * 32];     // [c][k] chunk
    __shared__ float sW2[32 * 128];   // [k][f] chunk
    int s = blockIdx.y;
    int l = 1 + (s >> 1);
    const float* W = ((s & 1) ? Wdst : Wsrc) + (size_t)l * 64 * 256;
    const float* W2l = W2 + (size_t)(s >> 1) * 256 * 1024;
    int f0 = blockIdx.x * 128;
    int t = threadIdx.x;
    int tf = t & 31;          // f = f0 + tf*4
    int tcg = t >> 5;         // c = tcg*8 + i
    float acc[8][4];
#pragma unroll
    for (int i = 0; i < 8; i++)
#pragma unroll
        for (int j = 0; j < 4; j++) acc[i][j] = 0.0f;

    for (int k0 = 0; k0 < 256; k0 += 32) {
        __syncthreads();
        for (int i = t; i < 64 * 32; i += 256) {
            int c = i >> 5, k = i & 31;
            sW[c * 32 + k] = W[c * 256 + k0 + k];
        }
        for (int i = t; i < 32 * 128; i += 256) {
            int k = i >> 7, f = i & 127;
            sW2[k * 128 + f] = W2l[(size_t)(k0 + k) * 1024 + f0 + f];
        }
        __syncthreads();
#pragma unroll 8
        for (int k = 0; k < 32; k++) {
            float4 w2 = *(const float4*)&sW2[k * 128 + tf * 4];
#pragma unroll
            for (int i = 0; i < 8; i++) {
                float a = sW[(tcg * 8 + i) * 32 + k];
                acc[i][0] = fmaf(a, w2.x, acc[i][0]);
                acc[i][1] = fmaf(a, w2.y, acc[i][1]);
                acc[i][2] = fmaf(a, w2.z, acc[i][2]);
                acc[i][3] = fmaf(a, w2.w, acc[i][3]);
            }
        }
    }
#pragma unroll
    for (int i = 0; i < 8; i++)
        *(float4*)&wc[(size_t)s * 64 * 1024 + (size_t)(tcg * 8 + i) * 1024 +
                      f0 + tf * 4] =
            make_float4(acc[i][0], acc[i][1], acc[i][2], acc[i][3]);
}

// ---------------- fused bias ----------------
__global__ void biasfold_kernel(const float* __restrict__ Wsrc,
                                const float* __restrict__ Wdst,
                                const float* __restrict__ bsrc,
                                const float* __restrict__ bdst,
                                const float* __restrict__ b2,
                                float* __restrict__ bx) {
    int which = blockIdx.x;
    int l = 1 + (which >> 1);
    bool isdst = which & 1;
    const float* W = (isdst ? Wdst : Wsrc) + (size_t)l * D_MSG * D_MODEL;
    const float* bb = (isdst ? bdst : bsrc) + (size_t)l * D_MSG;
    const float* b2p = b2 + (size_t)(l - 1) * D_MODEL;
    int c = threadIdx.x;
    float acc = bb[c];
    for (int k = 0; k < D_MODEL; k++) acc = fmaf(W[c * D_MODEL + k], b2p[k], acc);
    bx[which * D_MSG + c] = acc;
}

// ---------------- layer-0 projection gather ----------------
__global__ void gather_kernel(const int* __restrict__ an,
                              const float* __restrict__ es,
                              const float* __restrict__ ed,
                              float* __restrict__ xj,
                              float* __restrict__ xi) {
    int i = blockIdx.x;
    int c = threadIdx.x;
    int a = an[i];
    xj[i * D_MSG + c] = es[a * D_MSG + c];
    xi[i * D_MSG + c] = ed[a * D_MSG + c];
}

// ---------------- merged edge + triplet kernel ---------------------------------
// sWt stored at pitch 64 with XOR swizzle: off = b*64 + (ch4 ^ ((b&15)<<2)).
// Conflict-free fill (coalesced b-major) and float4 reads (contiguous per row).
#define ET_SMEM_FLOATS (256 * 64 + 64 * 17 + 16 * WIN + 48 + 64 + 256 + 16 * 4 + 32)
#define ET_SMEM_BYTES (ET_SMEM_FLOATS * 4)

__global__ void edge_triplet_kernel(const float* __restrict__ r,
                                    const int* __restrict__ src,
                                    const float* __restrict__ We,
                                    const float* __restrict__ bedge,
                                    const float* __restrict__ attn,
                                    const float* __restrict__ xj,
                                    const float* __restrict__ xi,
                                    float* __restrict__ xn) {
    extern __shared__ float sm[];
    float* sWt = sm;                           // [256][64] swizzled
    float* sx  = sm + 256 * 64;                // [64][17]  xij^T
    float* sy  = sx + 64 * 17;                 // [16][WIN]
    float* rh  = sy + 16 * WIN;                // [16][3]
    float* sat = rh + 48;                      // [64]
    float* sl  = sat + 64;                     // [16][16]
    float* mq  = sl + 256;                     // [16]
    float* zi  = mq + 16;
    float* wp  = zi + 16;
    float* sd  = wp + 16;
    int* sb0   = (int*)(sd + 16);
    int* ssrc  = sb0 + 16;

    int t = threadIdx.x;
    for (int idx = t; idx < 64 * 256; idx += 256) {
        int ch = idx >> 8, b = idx & 255;
        sWt[b * 64 + (ch ^ ((b & 15) << 2))] = We[idx];
    }
    if (t < 64) sat[t] = attn[t];
    int e_sub = t >> 4;
    int chv = t & 15;
    float4 bed = *(const float4*)&bedge[chv * 4];
    const float inv_step = 255.0f / 8.0f;
    const float step = 8.0f / 255.0f;
    const float gamma = inv_step;

    for (int g = blockIdx.x; g < N_NODES; g += gridDim.x) {
        __syncthreads();
        if (t < 16) {
            int e = g * 16 + t;
            float rx = r[e * 3 + 0], ry = r[e * 3 + 1], rz = r[e * 3 + 2];
            float d = sqrtf(rx * rx + ry * ry + rz * rz);
            float inv = 1.0f / d;
            rh[t * 3 + 0] = rx * inv;
            rh[t * 3 + 1] = ry * inv;
            rh[t * 3 + 2] = rz * inv;
            int cb = (int)(d * inv_step + 0.5f);
            int b0 = cb - WIN / 2;
            b0 = b0 < 0 ? 0 : (b0 > 256 - WIN ? 256 - WIN : b0);
            sb0[t] = b0;
            sd[t] = d;
            ssrc[t] = src[e];
        }
        __syncthreads();
        {   // Gaussian window, 2 bins/thread
            float d = sd[e_sub];
            int b0 = sb0[e_sub];
            int jb = chv * 2;
#pragma unroll
            for (int i = 0; i < 2; i++) {
                float tt = d - (float)(b0 + jb + i) * step;
                sy[e_sub * WIN + jb + i] = __expf(-gamma * tt * tt);
            }
        }
        __syncthreads();
        {   // windowed dot (f32x2 channel pairs) + gathers -> sx[ch][e]
            int b0 = sb0[e_sub];
            int ch4 = chv * 4;
            const float* yp = sy + e_sub * WIN;
            uint64_t a0 = pk2(bed.x, bed.y);
            uint64_t a1 = pk2(bed.z, bed.w);
#pragma unroll 16
            for (int j = 0; j < WIN; j++) {
                int row = b0 + j;
                float4 w = *(const float4*)&sWt[row * 64 +
                                                (ch4 ^ ((row & 15) << 2))];
                float yv = yp[j];
                uint64_t yd = pk2(yv, yv);
                ffma2(a0, yd, pk2(w.x, w.y));
                ffma2(a1, yd, pk2(w.z, w.w));
            }
            int sidx = ssrc[e_sub];
            float4 aj = *(const float4*)&xj[sidx * 64 + ch4];
            float4 ai = *(const float4*)&xi[g * 64 + ch4];
            float o0, o1, o2, o3;
            upk2(o0, o1, a0);
            upk2(o2, o3, a1);
            sx[(ch4 + 0) * 17 + e_sub] = o0 + aj.x + ai.x;
            sx[(ch4 + 1) * 17 + e_sub] = o1 + aj.y + ai.y;
            sx[(ch4 + 2) * 17 + e_sub] = o2 + aj.z + ai.z;
            sx[(ch4 + 3) * 17 + e_sub] = o3 + aj.w + ai.w;
        }
        __syncthreads();
        // triplet attention: 120 unordered pairs (symmetric logits)
        if (t < 120) {
            int q = (int)((1.0f + sqrtf(8.0f * (float)t + 1.0f)) * 0.5f);
            if (q * (q - 1) / 2 > t) q--;
            else if (q * (q + 1) / 2 <= t) q++;
            int p = t - q * (q - 1) / 2;

            float c = rh[p * 3 + 0] * rh[q * 3 + 0] +
                      rh[p * 3 + 1] * rh[q * 3 + 1] +
                      rh[p * 3 + 2] * rh[q * 3 + 2];
            c = fminf(fmaxf(c, -1.0f + 1e-6f), 1.0f - 1e-6f);
            float c2 = 2.0f * c;
            float t0 = 1.0f, t1 = c;
            float acc;
            {
                float s = 1.0f + sx[0 * 17 + p] + sx[0 * 17 + q];
                float si = __fdividef(s, 1.0f + __expf(-s));
                acc = sat[0] * si;
            }
#pragma unroll
            for (int k = 1; k < 64; k++) {
                float z = t1;
                float s = z + sx[k * 17 + p] + sx[k * 17 + q];
                float si = __fdividef(s, 1.0f + __expf(-s));
                acc = fmaf(sat[k], si, acc);
                float tn = fmaf(c2, t1, -t0);
                t0 = t1; t1 = tn;
            }
            sl[q * 16 + p] = acc;
            sl[p * 16 + q - 1] = acc;
        }
        __syncthreads();
        if (t < 16) {
            int q = t;
            float m = -1e30f;
#pragma unroll
            for (int ps = 0; ps < 15; ps++) m = fmaxf(m, sl[q * 16 + ps]);
            float z = 0.0f;
#pragma unroll
            for (int ps = 0; ps < 15; ps++) z += __expf(sl[q * 16 + ps] - m);
            mq[q] = m;
            zi[q] = __fdividef(1.0f, z);
        }
        __syncthreads();
        if (t < 16) {
            int p = t;
            float w = 0.0f;
#pragma unroll
            for (int q = 0; q < 16; q++) {
                if (q == p) continue;
                int ps = (p < q) ? p : p - 1;
                w += __expf(sl[q * 16 + ps] - mq[q]) * zi[q];
            }
            wp[p] = w;
        }
        __syncthreads();
        if (t < 64) {
            float acc = 0.0f;
#pragma unroll
            for (int p = 0; p < 16; p++) acc = fmaf(wp[p], sx[t * 17 + p], acc);
            xn[g * 64 + t] = acc;
        }
    }
}

// ---------------- SGEMM: C[M,N] = A[M,K] @ B[N,K]^T + bias ---------------------
// 128 threads, 64x64 tile, f32x2 row-pairs.
// EPI 1: silu(+bias)   EPI 3: dual (blockIdx.x selects B/bias/C; N=64)
template <int EPI>
__global__ __launch_bounds__(128)
void gemm64(const float* __restrict__ A,
            const float* __restrict__ B,
            float* __restrict__ C,
            int M, int N, int K,
            const float* __restrict__ bias,
            const float* __restrict__ B2,
            const float* __restrict__ bias2,
            float* __restrict__ C2) {
    __shared__ float As[32][64];
    __shared__ float Bs[32][64];
    int t = threadIdx.x;
    int n0 = blockIdx.x * 64;
    int m0 = blockIdx.y * 64;
    if (EPI == 3) {
        if (blockIdx.x == 1) { B = B2; bias = bias2; C = C2; }
        n0 = 0;
    }
    int r = t & 63;
    int kb = (t >> 6) * 16;
    int rg8 = (t >> 4) * 8;
    int cg4 = (t & 15) * 4;

    uint64_t acc2[4][4];
#pragma unroll
    for (int i = 0; i < 4; i++)
#pragma unroll
        for (int j = 0; j < 4; j++) acc2[i][j] = 0ull;

    int rowA = m0 + r;
    bool okA = rowA < M;
    const float* Ap = A + (size_t)(okA ? rowA : (M - 1)) * K + kb;
    const float* Bp = B + (size_t)(n0 + r) * K + kb;

    for (int k0 = 0; k0 < K; k0 += 32) {
        float4 av[4], bv[4];
#pragma unroll
        for (int i = 0; i < 4; i++) {
            av[i] = okA ? *(const float4*)(Ap + k0 + i * 4)
                        : make_float4(0.f, 0.f, 0.f, 0.f);
            bv[i] = *(const float4*)(Bp + k0 + i * 4);
        }
        __syncthreads();
#pragma unroll
        for (int i = 0; i < 4; i++) {
            As[kb + i * 4 + 0][r] = av[i].x;
            As[kb + i * 4 + 1][r] = av[i].y;
            As[kb + i * 4 + 2][r] = av[i].z;
            As[kb + i * 4 + 3][r] = av[i].w;
            Bs[kb + i * 4 + 0][r] = bv[i].x;
            Bs[kb + i * 4 + 1][r] = bv[i].y;
            Bs[kb + i * 4 + 2][r] = bv[i].z;
            Bs[kb + i * 4 + 3][r] = bv[i].w;
        }
        __syncthreads();
#pragma unroll 8
        for (int kk = 0; kk < 32; kk++) {
            float4 a0 = *(const float4*)&As[kk][rg8];
            float4 a1 = *(const float4*)&As[kk][rg8 + 4];
            float4 b = *(const float4*)&Bs[kk][cg4];
            uint64_t ap[4] = {pk2(a0.x, a0.y), pk2(a0.z, a0.w),
                              pk2(a1.x, a1.y), pk2(a1.z, a1.w)};
            uint64_t bd[4] = {pk2(b.x, b.x), pk2(b.y, b.y),
                              pk2(b.z, b.z), pk2(b.w, b.w)};
#pragma unroll
            for (int i = 0; i < 4; i++)
#pragma unroll
                for (int j = 0; j < 4; j++)
                    ffma2(acc2[i][j], ap[i], bd[j]);
        }
    }
    __syncthreads();

    float4 b4 = *(const float4*)&bias[n0 + cg4];
    float bb[4] = {b4.x, b4.y, b4.z, b4.w};
#pragma unroll
    for (int i = 0; i < 4; i++) {
        float v0[4], v1[4];
#pragma unroll
        for (int j = 0; j < 4; j++) {
            float lo, hi;
            upk2(lo, hi, acc2[i][j]);
            lo += bb[j];
            hi += bb[j];
            if (EPI == 1) {
                lo = __fdividef(lo, 1.0f + __expf(-lo));
                hi = __fdividef(hi, 1.0f + __expf(-hi));
            }
            v0[j] = lo;
            v1[j] = hi;
        }
        int m = m0 + rg8 + 2 * i;
        if (m < M)
            *(float4*)&C[(size_t)m * N + n0 + cg4] =
                make_float4(v0[0], v0[1], v0[2], v0[3]);
        if (m + 1 < M)
            *(float4*)&C[(size_t)(m + 1) * N + n0 + cg4] =
                make_float4(v1[0], v1[1], v1[2], v1[3]);
    }
}

// ---------------- head ----------------
__global__ void colsum1_kernel(const float* __restrict__ h,
                               float* __restrict__ hpart) {
    int f = blockIdx.y * 256 + threadIdx.x;
    int n0 = blockIdx.x * 100;
    float acc = 0.0f;
    for (int n = n0; n < n0 + 100; n++) acc += h[(size_t)n * D_FF + f];
    hpart[blockIdx.x * D_FF + f] = acc;
}

__global__ void colsum2_kernel(const float* __restrict__ hpart,
                               float* __restrict__ hsum) {
    int f = blockIdx.x * 256 + threadIdx.x;
    float acc = 0.0f;
    for (int b = 0; b < 60; b++) acc += hpart[b * D_FF + f];
    hsum[f] = acc;
}

__global__ void wfc2_kernel(const float* __restrict__ W2l2,
                            const float* __restrict__ Wfc,
                            float* __restrict__ wfc2) {
    int f = blockIdx.x * 256 + threadIdx.x;
    float acc = 0.0f;
    for (int k = 0; k < D_MODEL; k++)
        acc = fmaf(W2l2[(size_t)k * D_FF + f], Wfc[k], acc);
    wfc2[f] = acc;
}

__global__ void final_kernel(const float* __restrict__ hsum,
                             const float* __restrict__ wfc2,
                             const float* __restrict__ b2l2,
                             const float* __restrict__ Wfc,
                             const float* __restrict__ bfc,
                             float* __restrict__ out) {
    __shared__ float red[256];
    int t = threadIdx.x;
    float acc = 0.0f;
    for (int f = t; f < D_FF; f += 256) acc = fmaf(hsum[f], wfc2[f], acc);
    acc *= (1.0f / (float)N_NODES);
    acc = fmaf(b2l2[t], Wfc[t], acc);
    red[t] = acc;
    __syncthreads();
    for (int s = 128; s > 0; s >>= 1) {
        if (t < s) red[t] += red[t + s];
        __syncthreads();
    }
    if (t == 0) out[0] = red[0] + bfc[0];
}

// ---------------- launcher ----------------
extern "C" void kernel_launch(void* const* d_in, const int* in_sizes, int n_in,
                              void* d_out, int out_size) {
    const float* r     = (const float*)d_in[0];
    const int*   an    = (const int*)d_in[1];
    const int*   src   = (const int*)d_in[2];
    const float* emb   = (const float*)d_in[6];
    const float* Wsrc  = (const float*)d_in[7];
    const float* bsrc  = (const float*)d_in[8];
    const float* Wdst  = (const float*)d_in[9];
    const float* bdst  = (const float*)d_in[10];
    const float* Wedge = (const float*)d_in[11];
    const float* bedge = (const float*)d_in[12];
    const float* attn  = (const float*)d_in[13];
    const float* W1    = (const float*)d_in[14];
    const float* b1    = (const float*)d_in[15];
    const float* W2    = (const float*)d_in[16];
    const float* b2    = (const float*)d_in[17];
    const float* Wfc   = (const float*)d_in[18];
    const float* bfc   = (const float*)d_in[19];
    float* out = (float*)d_out;

    float *xj, *xi, *xn, *h, *wc, *es, *ed, *bx, *hpart, *hsum, *wfc2;
    cudaGetSymbolAddress((void**)&xj,   g_xj);
    cudaGetSymbolAddress((void**)&xi,   g_xi);
    cudaGetSymbolAddress((void**)&xn,   g_xn);
    cudaGetSymbolAddress((void**)&h,    g_h);
    cudaGetSymbolAddress((void**)&wc,   g_wc);
    cudaGetSymbolAddress((void**)&es,   g_embsrc);
    cudaGetSymbolAddress((void**)&ed,   g_embdst);
    cudaGetSymbolAddress((void**)&bx,   g_bx);
    cudaGetSymbolAddress((void**)&hpart, g_hpart);
    cudaGetSymbolAddress((void**)&hsum, g_hsum);
    cudaGetSymbolAddress((void**)&wfc2, g_wfc2);

    cudaFuncSetAttribute(edge_triplet_kernel,
                         cudaFuncAttributeMaxDynamicSharedMemorySize,
                         ET_SMEM_BYTES);

    // ---------- precompute ----------
    species_kernel<<<N_SPEC, 128>>>(emb, Wsrc, bsrc, Wdst, bdst, es, ed);
    wc_kernel<<<dim3(8, 4), 256>>>(Wsrc, Wdst, W2, wc);
    biasfold_kernel<<<4, 64>>>(Wsrc, Wdst, bsrc, bdst, b2, bx);
    gather_kernel<<<N_NODES, 64>>>(an, es, ed, xj, xi);

    const int MB_NODE = (N_NODES + 63) / 64;   // 94

    // ---------- layers ----------
    for (int l = 0; l < N_LAYERS; l++) {
        edge_triplet_kernel<<<444, 256, ET_SMEM_BYTES>>>(
            r, src, Wedge + l * 64 * 256, bedge + l * 64, attn + l * 64,
            xj, xi, xn);
        gemm64<1><<<dim3(16, MB_NODE), 128>>>(
            xn, W1 + l * D_FF * 64, h, N_NODES, D_FF, 64,
            b1 + l * D_FF, nullptr, nullptr, nullptr);
        if (l < 2) {
            gemm64<3><<<dim3(2, MB_NODE), 128>>>(
                h, wc + (size_t)(2 * l) * 64 * D_FF, xj, N_NODES, 64, D_FF,
                bx + 2 * l * 64,
                wc + (size_t)(2 * l + 1) * 64 * D_FF, bx + (2 * l + 1) * 64, xi);
        }
    }

    // ---------- head ----------
    colsum1_kernel<<<dim3(60, 4), 256>>>(h, hpart);
    colsum2_kernel<<<4, 256>>>(hpart, hsum);
    wfc2_kernel<<<4, 256>>>(W2 + 2 * D_MODEL * D_FF, Wfc, wfc2);
    final_kernel<<<1, 256>>>(hsum, wfc2, b2 + 2 * D_MODEL, Wfc, bfc, out);
}

// round 13
// speedup vs baseline: 1.0756x; 1.0646x over previous
#include <cuda_runtime.h>
#include <math.h>
#include <stdint.h>

#define N_NODES 6000
#define DEG 16
#define N_EDGES 96000
#define D_MODEL 256
#define D_MSG 64
#define D_FF 1024
#define N_LAYERS 3
#define RBF_BINS 256
#define WIN 32
#define N_SPEC 108

// ---------------- scratch (static device memory; no allocation) ----------------
__device__ float g_xj[N_NODES * D_MSG];
__device__ float g_xi[N_NODES * D_MSG];
__device__ float g_xij[N_EDGES * D_MSG];
__device__ float g_xn[N_NODES * D_MSG];
__device__ float g_h[N_NODES * D_FF];
__device__ float g_wc[4 * D_MSG * D_FF];
__device__ float g_embsrc[112 * D_MSG];
__device__ float g_embdst[112 * D_MSG];
__device__ float g_bx[4 * D_MSG];
__device__ float g_hpart[60 * D_FF];
__device__ float g_hsum[D_FF];
__device__ float g_wfc2[D_FF];

// ---------------- packed f32x2 helpers (sm_10x) ----------------
__device__ __forceinline__ uint64_t pk2(float lo, float hi) {
    uint64_t r;
    asm("mov.b64 %0, {%1, %2};" : "=l"(r) : "f"(lo), "f"(hi));
    return r;
}
__device__ __forceinline__ void upk2(float& lo, float& hi, uint64_t v) {
    asm("mov.b64 {%0, %1}, %2;" : "=f"(lo), "=f"(hi) : "l"(v));
}
__device__ __forceinline__ void ffma2(uint64_t& d, uint64_t a, uint64_t b) {
    asm("fma.rn.f32x2 %0, %1, %2, %0;" : "+l"(d) : "l"(a), "l"(b));
}

// ---------------- species projections: es/ed = emb @ W0^T + b ----------------
__global__ void species_kernel(const float* __restrict__ emb,
                               const float* __restrict__ Wsrc,
                               const float* __restrict__ bsrc,
                               const float* __restrict__ Wdst,
                               const float* __restrict__ bdst,
                               float* __restrict__ es,
                               float* __restrict__ ed) {
    __shared__ float se[256];
    int s = blockIdx.x;
    int t = threadIdx.x;
    se[t] = emb[s * 256 + t];
    se[t + 128] = emb[s * 256 + t + 128];
    __syncthreads();
    int c = t & 63;
    bool isdst = t >= 64;
    const float* W = (isdst ? Wdst : Wsrc) + c * 256;
    float acc = isdst ? bdst[c] : bsrc[c];
#pragma unroll 16
    for (int k = 0; k < 256; k += 4) {
        float4 w = *(const float4*)(W + k);
        acc = fmaf(se[k + 0], w.x, acc);
        acc = fmaf(se[k + 1], w.y, acc);
        acc = fmaf(se[k + 2], w.z, acc);
        acc = fmaf(se[k + 3], w.w, acc);
    }
    (isdst ? ed : es)[s * 64 + c] = acc;
}

// ---------------- fused weight precompute: wc[s] = W[s] @ W2[l(s)] ------------
__global__ void wc_kernel(const float* __restrict__ Wsrc,
                          const float* __restrict__ Wdst,
                          const float* __restrict__ W2,
                          float* __restrict__ wc) {
    __shared__ float sW[64 * 32];
    __shared__ float sW2[32 * 128];
    int s = blockIdx.y;
    int l = 1 + (s >> 1);
    const float* W = ((s & 1) ? Wdst : Wsrc) + (size_t)l * 64 * 256;
    const float* W2l = W2 + (size_t)(s >> 1) * 256 * 1024;
    int f0 = blockIdx.x * 128;
    int t = threadIdx.x;
    int tf = t & 31;
    int tcg = t >> 5;
    float acc[8][4];
#pragma unroll
    for (int i = 0; i < 8; i++)
#pragma unroll
        for (int j = 0; j < 4; j++) acc[i][j] = 0.0f;

    for (int k0 = 0; k0 < 256; k0 += 32) {
        __syncthreads();
        for (int i = t; i < 64 * 32; i += 256) {
            int c = i >> 5, k = i & 31;
            sW[c * 32 + k] = W[c * 256 + k0 + k];
        }
        for (int i = t; i < 32 * 128; i += 256) {
            int k = i >> 7, f = i & 127;
            sW2[k * 128 + f] = W2l[(size_t)(k0 + k) * 1024 + f0 + f];
        }
        __syncthreads();
#pragma unroll 8
        for (int k = 0; k < 32; k++) {
            float4 w2 = *(const float4*)&sW2[k * 128 + tf * 4];
#pragma unroll
            for (int i = 0; i < 8; i++) {
                float a = sW[(tcg * 8 + i) * 32 + k];
                acc[i][0] = fmaf(a, w2.x, acc[i][0]);
                acc[i][1] = fmaf(a, w2.y, acc[i][1]);
                acc[i][2] = fmaf(a, w2.z, acc[i][2]);
                acc[i][3] = fmaf(a, w2.w, acc[i][3]);
            }
        }
    }
#pragma unroll
    for (int i = 0; i < 8; i++)
        *(float4*)&wc[(size_t)s * 64 * 1024 + (size_t)(tcg * 8 + i) * 1024 +
                      f0 + tf * 4] =
            make_float4(acc[i][0], acc[i][1], acc[i][2], acc[i][3]);
}

// ---------------- fused bias ----------------
__global__ void biasfold_kernel(const float* __restrict__ Wsrc,
                                const float* __restrict__ Wdst,
                                const float* __restrict__ bsrc,
                                const float* __restrict__ bdst,
                                const float* __restrict__ b2,
                                float* __restrict__ bx) {
    int which = blockIdx.x;
    int l = 1 + (which >> 1);
    bool isdst = which & 1;
    const float* W = (isdst ? Wdst : Wsrc) + (size_t)l * D_MSG * D_MODEL;
    const float* bb = (isdst ? bdst : bsrc) + (size_t)l * D_MSG;
    const float* b2p = b2 + (size_t)(l - 1) * D_MODEL;
    int c = threadIdx.x;
    float acc = bb[c];
    for (int k = 0; k < D_MODEL; k++) acc = fmaf(W[c * D_MODEL + k], b2p[k], acc);
    bx[which * D_MSG + c] = acc;
}

// ---------------- layer-0 projection gather ----------------
__global__ void gather_kernel(const int* __restrict__ an,
                              const float* __restrict__ es,
                              const float* __restrict__ ed,
                              float* __restrict__ xj,
                              float* __restrict__ xi) {
    int i = blockIdx.x;
    int c = threadIdx.x;
    int a = an[i];
    xj[i * D_MSG + c] = es[a * D_MSG + c];
    xi[i * D_MSG + c] = ed[a * D_MSG + c];
}

// ---------------- fused windowed-RBF edge kernel (standalone, f32x2 dot) ------
#define EDGE_WPITCH 68
#define EDGE_SMEM_BYTES (256 * EDGE_WPITCH * 4 + 16 * WIN * 4 + 16 * 4 * 3)

__global__ void edge_kernel(const float* __restrict__ r,
                            const int* __restrict__ src,
                            const float* __restrict__ We,     // [64,256]
                            const float* __restrict__ bedge,  // [64]
                            const float* __restrict__ xj,
                            const float* __restrict__ xi,
                            float* __restrict__ xij) {
    extern __shared__ float sm[];
    float* sWt = sm;                        // [256][68] transposed Wedge
    float* sy = sm + 256 * EDGE_WPITCH;     // [16][WIN]
    int* sb0 = (int*)(sy + 16 * WIN);
    int* ssrc = sb0 + 16;
    float* sd = (float*)(ssrc + 16);

    int t = threadIdx.x;
    for (int idx = t; idx < 64 * 256; idx += 256) {
        int ch = idx >> 8, b = idx & 255;
        sWt[b * EDGE_WPITCH + ch] = We[idx];
    }
    int e_sub = t >> 4;
    int chv = t & 15;
    float4 bed = *(const float4*)&bedge[chv * 4];
    const float inv_step = 255.0f / 8.0f;
    const float step = 8.0f / 255.0f;
    const float gamma = inv_step;

    for (int g = blockIdx.x; g < N_NODES; g += gridDim.x) {
        __syncthreads();
        if (t < 16) {
            int e = g * 16 + t;
            float rx = r[e * 3 + 0], ry = r[e * 3 + 1], rz = r[e * 3 + 2];
            float d = sqrtf(rx * rx + ry * ry + rz * rz);
            int cb = (int)(d * inv_step + 0.5f);
            int b0 = cb - WIN / 2;
            b0 = b0 < 0 ? 0 : (b0 > 256 - WIN ? 256 - WIN : b0);
            sb0[t] = b0;
            sd[t] = d;
            ssrc[t] = src[e];
        }
        __syncthreads();
        {
            float d = sd[e_sub];
            int b0 = sb0[e_sub];
            int jb = chv * 2;
#pragma unroll
            for (int i = 0; i < 2; i++) {
                float tt = d - (float)(b0 + jb + i) * step;
                sy[e_sub * WIN + jb + i] = __expf(-gamma * tt * tt);
            }
        }
        __syncthreads();
        {
            int b0 = sb0[e_sub];
            const float* wp = sWt + (size_t)b0 * EDGE_WPITCH + chv * 4;
            const float* yp = sy + e_sub * WIN;
            uint64_t a0 = pk2(bed.x, bed.y);
            uint64_t a1 = pk2(bed.z, bed.w);
#pragma unroll 16
            for (int j = 0; j < WIN; j++) {
                float yv = yp[j];
                uint64_t yd = pk2(yv, yv);
                float4 w = *(const float4*)(wp + (size_t)j * EDGE_WPITCH);
                ffma2(a0, yd, pk2(w.x, w.y));
                ffma2(a1, yd, pk2(w.z, w.w));
            }
            int sidx = ssrc[e_sub];
            float4 aj = *(const float4*)&xj[sidx * 64 + chv * 4];
            float4 ai = *(const float4*)&xi[g * 64 + chv * 4];
            float o0, o1, o2, o3;
            upk2(o0, o1, a0);
            upk2(o2, o3, a1);
            float4 res = make_float4(o0 + aj.x + ai.x, o1 + aj.y + ai.y,
                                     o2 + aj.z + ai.z, o3 + aj.w + ai.w);
            *(float4*)&xij[(size_t)(g * 16 + e_sub) * 64 + chv * 4] = res;
        }
    }
}

// ---------------- per-node triplet attention (symmetric, inline rhat) ---------
__global__ void triplet_kernel(const float* __restrict__ xij,
                               const float* __restrict__ r,
                               const float* __restrict__ attn,
                               float* __restrict__ xn) {
    __shared__ float sx[64][17];
    __shared__ float rh[16][3];
    __shared__ float sat[64];
    __shared__ float sl[16][16];
    __shared__ float mq[16], zi[16], wp[16];

    int node = blockIdx.x;
    int t = threadIdx.x;
    const float* xb = xij + (size_t)node * 16 * 64;

    for (int idx = t; idx < 1024; idx += 256) {
        int p = idx >> 6, k = idx & 63;
        sx[k][p] = xb[idx];
    }
    if (t < 16) {
        int e = node * 16 + t;
        float rx = r[e * 3 + 0], ry = r[e * 3 + 1], rz = r[e * 3 + 2];
        float inv = rsqrtf(rx * rx + ry * ry + rz * rz);
        rh[t][0] = rx * inv;
        rh[t][1] = ry * inv;
        rh[t][2] = rz * inv;
    }
    if (t < 64) sat[t] = attn[t];
    __syncthreads();

    if (t < 120) {
        int q = (int)((1.0f + sqrtf(8.0f * (float)t + 1.0f)) * 0.5f);
        if (q * (q - 1) / 2 > t) q--;
        else if (q * (q + 1) / 2 <= t) q++;
        int p = t - q * (q - 1) / 2;

        float c = rh[p][0] * rh[q][0] + rh[p][1] * rh[q][1] + rh[p][2] * rh[q][2];
        c = fminf(fmaxf(c, -1.0f + 1e-6f), 1.0f - 1e-6f);
        float c2 = 2.0f * c;
        float t0 = 1.0f, t1 = c;
        float acc;
        {
            float s = 1.0f + sx[0][p] + sx[0][q];
            float si = __fdividef(s, 1.0f + __expf(-s));
            acc = sat[0] * si;
        }
#pragma unroll
        for (int k = 1; k < 64; k++) {
            float z = t1;
            float s = z + sx[k][p] + sx[k][q];
            float si = __fdividef(s, 1.0f + __expf(-s));
            acc = fmaf(sat[k], si, acc);
            float tn = fmaf(c2, t1, -t0);
            t0 = t1; t1 = tn;
        }
        sl[q][p] = acc;
        sl[p][q - 1] = acc;
    }
    __syncthreads();

    if (t < 16) {
        int q = t;
        float m = -1e30f;
#pragma unroll
        for (int ps = 0; ps < 15; ps++) m = fmaxf(m, sl[q][ps]);
        float z = 0.0f;
#pragma unroll
        for (int ps = 0; ps < 15; ps++) z += __expf(sl[q][ps] - m);
        mq[q] = m;
        zi[q] = __fdividef(1.0f, z);
    }
    __syncthreads();

    if (t < 16) {
        int p = t;
        float w = 0.0f;
#pragma unroll
        for (int q = 0; q < 16; q++) {
            if (q == p) continue;
            int ps = (p < q) ? p : p - 1;
            w += __expf(sl[q][ps] - mq[q]) * zi[q];
        }
        wp[p] = w;
    }
    __syncthreads();

    if (t < 64) {
        int k = t;
        float acc = 0.0f;
#pragma unroll
        for (int p = 0; p < 16; p++) acc = fmaf(wp[p], sx[k][p], acc);
        xn[node * 64 + k] = acc;
    }
}

// ---------------- SGEMM: C[M,N] = A[M,K] @ B[N,K]^T + bias ---------------------
// EPI 1: silu(+bias)   EPI 3: dual (blockIdx.x selects B/bias/C; N=64)
template <int EPI>
__global__ __launch_bounds__(128)
void gemm64(const float* __restrict__ A,
            const float* __restrict__ B,
            float* __restrict__ C,
            int M, int N, int K,
            const float* __restrict__ bias,
            const float* __restrict__ B2,
            const float* __restrict__ bias2,
            float* __restrict__ C2) {
    __shared__ float As[32][64];
    __shared__ float Bs[32][64];
    int t = threadIdx.x;
    int n0 = blockIdx.x * 64;
    int m0 = blockIdx.y * 64;
    if (EPI == 3) {
        if (blockIdx.x == 1) { B = B2; bias = bias2; C = C2; }
        n0 = 0;
    }
    int r = t & 63;
    int kb = (t >> 6) * 16;
    int rg8 = (t >> 4) * 8;
    int cg4 = (t & 15) * 4;

    uint64_t acc2[4][4];
#pragma unroll
    for (int i = 0; i < 4; i++)
#pragma unroll
        for (int j = 0; j < 4; j++) acc2[i][j] = 0ull;

    int rowA = m0 + r;
    bool okA = rowA < M;
    const float* Ap = A + (size_t)(okA ? rowA : (M - 1)) * K + kb;
    const float* Bp = B + (size_t)(n0 + r) * K + kb;

    for (int k0 = 0; k0 < K; k0 += 32) {
        float4 av[4], bv[4];
#pragma unroll
        for (int i = 0; i < 4; i++) {
            av[i] = okA ? *(const float4*)(Ap + k0 + i * 4)
                        : make_float4(0.f, 0.f, 0.f, 0.f);
            bv[i] = *(const float4*)(Bp + k0 + i * 4);
        }
        __syncthreads();
#pragma unroll
        for (int i = 0; i < 4; i++) {
            As[kb + i * 4 + 0][r] = av[i].x;
            As[kb + i * 4 + 1][r] = av[i].y;
            As[kb + i * 4 + 2][r] = av[i].z;
            As[kb + i * 4 + 3][r] = av[i].w;
            Bs[kb + i * 4 + 0][r] = bv[i].x;
            Bs[kb + i * 4 + 1][r] = bv[i].y;
            Bs[kb + i * 4 + 2][r] = bv[i].z;
            Bs[kb + i * 4 + 3][r] = bv[i].w;
        }
        __syncthreads();
#pragma unroll 8
        for (int kk = 0; kk < 32; kk++) {
            float4 a0 = *(const float4*)&As[kk][rg8];
            float4 a1 = *(const float4*)&As[kk][rg8 + 4];
            float4 b = *(const float4*)&Bs[kk][cg4];
            uint64_t ap[4] = {pk2(a0.x, a0.y), pk2(a0.z, a0.w),
                              pk2(a1.x, a1.y), pk2(a1.z, a1.w)};
            uint64_t bd[4] = {pk2(b.x, b.x), pk2(b.y, b.y),
                              pk2(b.z, b.z), pk2(b.w, b.w)};
#pragma unroll
            for (int i = 0; i < 4; i++)
#pragma unroll
                for (int j = 0; j < 4; j++)
                    ffma2(acc2[i][j], ap[i], bd[j]);
        }
    }
    __syncthreads();

    float4 b4 = *(const float4*)&bias[n0 + cg4];
    float bb[4] = {b4.x, b4.y, b4.z, b4.w};
#pragma unroll
    for (int i = 0; i < 4; i++) {
        float v0[4], v1[4];
#pragma unroll
        for (int j = 0; j < 4; j++) {
            float lo, hi;
            upk2(lo, hi, acc2[i][j]);
            lo += bb[j];
            hi += bb[j];
            if (EPI == 1) {
                lo = __fdividef(lo, 1.0f + __expf(-lo));
                hi = __fdividef(hi, 1.0f + __expf(-hi));
            }
            v0[j] = lo;
            v1[j] = hi;
        }
        int m = m0 + rg8 + 2 * i;
        if (m < M)
            *(float4*)&C[(size_t)m * N + n0 + cg4] =
                make_float4(v0[0], v0[1], v0[2], v0[3]);
        if (m + 1 < M)
            *(float4*)&C[(size_t)(m + 1) * N + n0 + cg4] =
                make_float4(v1[0], v1[1], v1[2], v1[3]);
    }
}

// ---------------- head ----------------
__global__ void colsum1_kernel(const float* __restrict__ h,
                               float* __restrict__ hpart) {
    int f = blockIdx.y * 256 + threadIdx.x;
    int n0 = blockIdx.x * 100;
    float acc = 0.0f;
    for (int n = n0; n < n0 + 100; n++) acc += h[(size_t)n * D_FF + f];
    hpart[blockIdx.x * D_FF + f] = acc;
}

__global__ void colsum2_kernel(const float* __restrict__ hpart,
                               float* __restrict__ hsum) {
    int f = blockIdx.x * 256 + threadIdx.x;
    float acc = 0.0f;
    for (int b = 0; b < 60; b++) acc += hpart[b * D_FF + f];
    hsum[f] = acc;
}

__global__ void wfc2_kernel(const float* __restrict__ W2l2,
                            const float* __restrict__ Wfc,
                            float* __restrict__ wfc2) {
    int f = blockIdx.x * 256 + threadIdx.x;
    float acc = 0.0f;
    for (int k = 0; k < D_MODEL; k++)
        acc = fmaf(W2l2[(size_t)k * D_FF + f], Wfc[k], acc);
    wfc2[f] = acc;
}

__global__ void final_kernel(const float* __restrict__ hsum,
                             const float* __restrict__ wfc2,
                             const float* __restrict__ b2l2,
                             const float* __restrict__ Wfc,
                             const float* __restrict__ bfc,
                             float* __restrict__ out) {
    __shared__ float red[256];
    int t = threadIdx.x;
    float acc = 0.0f;
    for (int f = t; f < D_FF; f += 256) acc = fmaf(hsum[f], wfc2[f], acc);
    acc *= (1.0f / (float)N_NODES);
    acc = fmaf(b2l2[t], Wfc[t], acc);
    red[t] = acc;
    __syncthreads();
    for (int s = 128; s > 0; s >>= 1) {
        if (t < s) red[t] += red[t + s];
        __syncthreads();
    }
    if (t == 0) out[0] = red[0] + bfc[0];
}

// ---------------- launcher ----------------
extern "C" void kernel_launch(void* const* d_in, const int* in_sizes, int n_in,
                              void* d_out, int out_size) {
    const float* r     = (const float*)d_in[0];
    const int*   an    = (const int*)d_in[1];
    const int*   src   = (const int*)d_in[2];
    const float* emb   = (const float*)d_in[6];
    const float* Wsrc  = (const float*)d_in[7];
    const float* bsrc  = (const float*)d_in[8];
    const float* Wdst  = (const float*)d_in[9];
    const float* bdst  = (const float*)d_in[10];
    const float* Wedge = (const float*)d_in[11];
    const float* bedge = (const float*)d_in[12];
    const float* attn  = (const float*)d_in[13];
    const float* W1    = (const float*)d_in[14];
    const float* b1    = (const float*)d_in[15];
    const float* W2    = (const float*)d_in[16];
    const float* b2    = (const float*)d_in[17];
    const float* Wfc   = (const float*)d_in[18];
    const float* bfc   = (const float*)d_in[19];
    float* out = (float*)d_out;

    float *xj, *xi, *xij, *xn, *h, *wc, *es, *ed, *bx, *hpart, *hsum, *wfc2;
    cudaGetSymbolAddress((void**)&xj,   g_xj);
    cudaGetSymbolAddress((void**)&xi,   g_xi);
    cudaGetSymbolAddress((void**)&xij,  g_xij);
    cudaGetSymbolAddress((void**)&xn,   g_xn);
    cudaGetSymbolAddress((void**)&h,    g_h);
    cudaGetSymbolAddress((void**)&wc,   g_wc);
    cudaGetSymbolAddress((void**)&es,   g_embsrc);
    cudaGetSymbolAddress((void**)&ed,   g_embdst);
    cudaGetSymbolAddress((void**)&bx,   g_bx);
    cudaGetSymbolAddress((void**)&hpart, g_hpart);
    cudaGetSymbolAddress((void**)&hsum, g_hsum);
    cudaGetSymbolAddress((void**)&wfc2, g_wfc2);

    cudaFuncSetAttribute(edge_kernel,
                         cudaFuncAttributeMaxDynamicSharedMemorySize,
                         EDGE_SMEM_BYTES);

    // ---------- precompute ----------
    species_kernel<<<N_SPEC, 128>>>(emb, Wsrc, bsrc, Wdst, bdst, es, ed);
    wc_kernel<<<dim3(8, 4), 256>>>(Wsrc, Wdst, W2, wc);
    biasfold_kernel<<<4, 64>>>(Wsrc, Wdst, bsrc, bdst, b2, bx);
    gather_kernel<<<N_NODES, 64>>>(an, es, ed, xj, xi);

    const int MB_NODE = (N_NODES + 63) / 64;   // 94

    // ---------- layers ----------
    for (int l = 0; l < N_LAYERS; l++) {
        edge_kernel<<<444, 256, EDGE_SMEM_BYTES>>>(
            r, src, Wedge + l * 64 * 256, bedge + l * 64, xj, xi, xij);
        triplet_kernel<<<N_NODES, 256>>>(xij, r, attn + l * 64, xn);
        gemm64<1><<<dim3(16, MB_NODE), 128>>>(
            xn, W1 + l * D_FF * 64, h, N_NODES, D_FF, 64,
            b1 + l * D_FF, nullptr, nullptr, nullptr);
        if (l < 2) {
            gemm64<3><<<dim3(2, MB_NODE), 128>>>(
                h, wc + (size_t)(2 * l) * 64 * D_FF, xj, N_NODES, 64, D_FF,
                bx + 2 * l * 64,
                wc + (size_t)(2 * l + 1) * 64 * D_FF, bx + (2 * l + 1) * 64, xi);
        }
    }

    // ---------- head ----------
    colsum1_kernel<<<dim3(60, 4), 256>>>(h, hpart);
    colsum2_kernel<<<4, 256>>>(hpart, hsum);
    wfc2_kernel<<<4, 256>>>(W2 + 2 * D_MODEL * D_FF, Wfc, wfc2);
    final_kernel<<<1, 256>>>(hsum, wfc2, b2 + 2 * D_MODEL, Wfc, bfc, out);
}

// round 14
// speedup vs baseline: 1.1373x; 1.0574x over previous
#include <cuda_runtime.h>
#include <math.h>
#include <stdint.h>

#define N_NODES 6000
#define DEG 16
#define N_EDGES 96000
#define D_MODEL 256
#define D_MSG 64
#define D_FF 1024
#define N_LAYERS 3
#define RBF_BINS 256
#define WIN 32
#define N_SPEC 108

// ---------------- scratch (static device memory; no allocation) ----------------
__device__ float g_xj[N_NODES * D_MSG];
__device__ float g_xi[N_NODES * D_MSG];
__device__ float g_xjsplit[4 * N_NODES * D_MSG];
__device__ float g_xij[N_EDGES * D_MSG];
__device__ float g_xn[N_NODES * D_MSG];
__device__ float g_h[N_NODES * D_FF];
__device__ float g_wc[4 * D_MSG * D_FF];
__device__ float g_embsrc[112 * D_MSG];
__device__ float g_embdst[112 * D_MSG];
__device__ float g_bx[4 * D_MSG];
__device__ float g_hpart[60 * D_FF];
__device__ float g_wfc2[D_FF];
__device__ float g_zeros[D_FF];            // zero-initialized

// ---------------- packed f32x2 helpers (sm_10x) ----------------
__device__ __forceinline__ uint64_t pk2(float lo, float hi) {
    uint64_t r;
    asm("mov.b64 %0, {%1, %2};" : "=l"(r) : "f"(lo), "f"(hi));
    return r;
}
__device__ __forceinline__ void upk2(float& lo, float& hi, uint64_t v) {
    asm("mov.b64 {%0, %1}, %2;" : "=f"(lo), "=f"(hi) : "l"(v));
}
__device__ __forceinline__ void ffma2(uint64_t& d, uint64_t a, uint64_t b) {
    asm("fma.rn.f32x2 %0, %1, %2, %0;" : "+l"(d) : "l"(a), "l"(b));
}

// ---------------- species projections: es/ed = emb @ W0^T + b ----------------
__global__ void species_kernel(const float* __restrict__ emb,
                               const float* __restrict__ Wsrc,
                               const float* __restrict__ bsrc,
                               const float* __restrict__ Wdst,
                               const float* __restrict__ bdst,
                               float* __restrict__ es,
                               float* __restrict__ ed) {
    __shared__ float se[256];
    int s = blockIdx.x;
    int t = threadIdx.x;
    se[t] = emb[s * 256 + t];
    se[t + 128] = emb[s * 256 + t + 128];
    __syncthreads();
    int c = t & 63;
    bool isdst = t >= 64;
    const float* W = (isdst ? Wdst : Wsrc) + c * 256;
    float acc = isdst ? bdst[c] : bsrc[c];
#pragma unroll 16
    for (int k = 0; k < 256; k += 4) {
        float4 w = *(const float4*)(W + k);
        acc = fmaf(se[k + 0], w.x, acc);
        acc = fmaf(se[k + 1], w.y, acc);
        acc = fmaf(se[k + 2], w.z, acc);
        acc = fmaf(se[k + 3], w.w, acc);
    }
    (isdst ? ed : es)[s * 64 + c] = acc;
}

// ---------------- fused weight precompute: wc[s] = W[s] @ W2[l(s)] ------------
__global__ void wc_kernel(const float* __restrict__ Wsrc,
                          const float* __restrict__ Wdst,
                          const float* __restrict__ W2,
                          float* __restrict__ wc) {
    __shared__ float sW[64 * 32];
    __shared__ float sW2[32 * 128];
    int s = blockIdx.y;
    int l = 1 + (s >> 1);
    const float* W = ((s & 1) ? Wdst : Wsrc) + (size_t)l * 64 * 256;
    const float* W2l = W2 + (size_t)(s >> 1) * 256 * 1024;
    int f0 = blockIdx.x * 128;
    int t = threadIdx.x;
    int tf = t & 31;
    int tcg = t >> 5;
    float acc[8][4];
#pragma unroll
    for (int i = 0; i < 8; i++)
#pragma unroll
        for (int j = 0; j < 4; j++) acc[i][j] = 0.0f;

    for (int k0 = 0; k0 < 256; k0 += 32) {
        __syncthreads();
        for (int i = t; i < 64 * 32; i += 256) {
            int c = i >> 5, k = i & 31;
            sW[c * 32 + k] = W[c * 256 + k0 + k];
        }
        for (int i = t; i < 32 * 128; i += 256) {
            int k = i >> 7, f = i & 127;
            sW2[k * 128 + f] = W2l[(size_t)(k0 + k) * 1024 + f0 + f];
        }
        __syncthreads();
#pragma unroll 8
        for (int k = 0; k < 32; k++) {
            float4 w2 = *(const float4*)&sW2[k * 128 + tf * 4];
#pragma unroll
            for (int i = 0; i < 8; i++) {
                float a = sW[(tcg * 8 + i) * 32 + k];
                acc[i][0] = fmaf(a, w2.x, acc[i][0]);
                acc[i][1] = fmaf(a, w2.y, acc[i][1]);
                acc[i][2] = fmaf(a, w2.z, acc[i][2]);
                acc[i][3] = fmaf(a, w2.w, acc[i][3]);
            }
        }
    }
#pragma unroll
    for (int i = 0; i < 8; i++)
        *(float4*)&wc[(size_t)s * 64 * 1024 + (size_t)(tcg * 8 + i) * 1024 +
                      f0 + tf * 4] =
            make_float4(acc[i][0], acc[i][1], acc[i][2], acc[i][3]);
}

// ---------------- fused bias ----------------
__global__ void biasfold_kernel(const float* __restrict__ Wsrc,
                                const float* __restrict__ Wdst,
                                const float* __restrict__ bsrc,
                                const float* __restrict__ bdst,
                                const float* __restrict__ b2,
                                float* __restrict__ bx) {
    int which = blockIdx.x;
    int l = 1 + (which >> 1);
    bool isdst = which & 1;
    const float* W = (isdst ? Wdst : Wsrc) + (size_t)l * D_MSG * D_MODEL;
    const float* bb = (isdst ? bdst : bsrc) + (size_t)l * D_MSG;
    const float* b2p = b2 + (size_t)(l - 1) * D_MODEL;
    int c = threadIdx.x;
    float acc = bb[c];
    for (int k = 0; k < D_MODEL; k++) acc = fmaf(W[c * D_MODEL + k], b2p[k], acc);
    bx[which * D_MSG + c] = acc;
}

// ---------------- wfc2[f] = sum_k W2_2[k][f] * Wfc[k] (precompute) ------------
__global__ void wfc2_kernel(const float* __restrict__ W2l2,
                            const float* __restrict__ Wfc,
                            float* __restrict__ wfc2) {
    int f = blockIdx.x * 256 + threadIdx.x;
    float acc = 0.0f;
    for (int k = 0; k < D_MODEL; k++)
        acc = fmaf(W2l2[(size_t)k * D_FF + f], Wfc[k], acc);
    wfc2[f] = acc;
}

// ---------------- layer-0 projection gather ----------------
__global__ void gather_kernel(const int* __restrict__ an,
                              const float* __restrict__ es,
                              const float* __restrict__ ed,
                              float* __restrict__ xj,
                              float* __restrict__ xi) {
    int i = blockIdx.x;
    int c = threadIdx.x;
    int a = an[i];
    xj[i * D_MSG + c] = es[a * D_MSG + c];
    xi[i * D_MSG + c] = ed[a * D_MSG + c];
}

// ---------------- fused windowed-RBF edge kernel (f32x2 dot) ------------------
#define EDGE_WPITCH 68
#define EDGE_SMEM_BYTES (256 * EDGE_WPITCH * 4 + 16 * WIN * 4 + 16 * 4 * 3)

__global__ void edge_kernel(const float* __restrict__ r,
                            const int* __restrict__ src,
                            const float* __restrict__ We,
                            const float* __restrict__ bedge,
                            const float* __restrict__ xj,
                            const float* __restrict__ xi,
                            float* __restrict__ xij) {
    extern __shared__ float sm[];
    float* sWt = sm;
    float* sy = sm + 256 * EDGE_WPITCH;
    int* sb0 = (int*)(sy + 16 * WIN);
    int* ssrc = sb0 + 16;
    float* sd = (float*)(ssrc + 16);

    int t = threadIdx.x;
    for (int idx = t; idx < 64 * 256; idx += 256) {
        int ch = idx >> 8, b = idx & 255;
        sWt[b * EDGE_WPITCH + ch] = We[idx];
    }
    int e_sub = t >> 4;
    int chv = t & 15;
    float4 bed = *(const float4*)&bedge[chv * 4];
    const float inv_step = 255.0f / 8.0f;
    const float step = 8.0f / 255.0f;
    const float gamma = inv_step;

    for (int g = blockIdx.x; g < N_NODES; g += gridDim.x) {
        __syncthreads();
        if (t < 16) {
            int e = g * 16 + t;
            float rx = r[e * 3 + 0], ry = r[e * 3 + 1], rz = r[e * 3 + 2];
            float d = sqrtf(rx * rx + ry * ry + rz * rz);
            int cb = (int)(d * inv_step + 0.5f);
            int b0 = cb - WIN / 2;
            b0 = b0 < 0 ? 0 : (b0 > 256 - WIN ? 256 - WIN : b0);
            sb0[t] = b0;
            sd[t] = d;
            ssrc[t] = src[e];
        }
        __syncthreads();
        {
            float d = sd[e_sub];
            int b0 = sb0[e_sub];
            int jb = chv * 2;
#pragma unroll
            for (int i = 0; i < 2; i++) {
                float tt = d - (float)(b0 + jb + i) * step;
                sy[e_sub * WIN + jb + i] = __expf(-gamma * tt * tt);
            }
        }
        __syncthreads();
        {
            int b0 = sb0[e_sub];
            const float* wp = sWt + (size_t)b0 * EDGE_WPITCH + chv * 4;
            const float* yp = sy + e_sub * WIN;
            uint64_t a0 = pk2(bed.x, bed.y);
            uint64_t a1 = pk2(bed.z, bed.w);
#pragma unroll 16
            for (int j = 0; j < WIN; j++) {
                float yv = yp[j];
                uint64_t yd = pk2(yv, yv);
                float4 w = *(const float4*)(wp + (size_t)j * EDGE_WPITCH);
                ffma2(a0, yd, pk2(w.x, w.y));
                ffma2(a1, yd, pk2(w.z, w.w));
            }
            int sidx = ssrc[e_sub];
            float4 aj = *(const float4*)&xj[sidx * 64 + chv * 4];
            float4 ai = *(const float4*)&xi[g * 64 + chv * 4];
            float o0, o1, o2, o3;
            upk2(o0, o1, a0);
            upk2(o2, o3, a1);
            float4 res = make_float4(o0 + aj.x + ai.x, o1 + aj.y + ai.y,
                                     o2 + aj.z + ai.z, o3 + aj.w + ai.w);
            *(float4*)&xij[(size_t)(g * 16 + e_sub) * 64 + chv * 4] = res;
        }
    }
}

// ---------------- triplet attention: 2 nodes per 256-thread block -------------
__global__ void triplet_kernel(const float* __restrict__ xij,
                               const float* __restrict__ r,
                               const float* __restrict__ attn,
                               float* __restrict__ xn) {
    __shared__ float sx[2][64][17];
    __shared__ float rh[2][16][3];
    __shared__ float sat[64];
    __shared__ float sl[2][16][16];
    __shared__ float mq[2][16], zi[2][16], wp[2][16];

    int n0 = blockIdx.x * 2;
    int t = threadIdx.x;
    const float* xb = xij + (size_t)n0 * 16 * 64;   // 2048 contiguous floats

    for (int idx = t; idx < 2048; idx += 256) {
        int nd = idx >> 10, p = (idx >> 6) & 15, k = idx & 63;
        sx[nd][k][p] = xb[idx];
    }
    if (t < 32) {
        int e = n0 * 16 + t;
        float rx = r[e * 3 + 0], ry = r[e * 3 + 1], rz = r[e * 3 + 2];
        float inv = rsqrtf(rx * rx + ry * ry + rz * rz);
        int nd = t >> 4, le = t & 15;
        rh[nd][le][0] = rx * inv;
        rh[nd][le][1] = ry * inv;
        rh[nd][le][2] = rz * inv;
    }
    if (t < 64) sat[t] = attn[t];
    __syncthreads();

    if (t < 240) {
        int nd = t / 120;
        int tt = t - nd * 120;
        int q = (int)((1.0f + sqrtf(8.0f * (float)tt + 1.0f)) * 0.5f);
        if (q * (q - 1) / 2 > tt) q--;
        else if (q * (q + 1) / 2 <= tt) q++;
        int p = tt - q * (q - 1) / 2;

        float c = rh[nd][p][0] * rh[nd][q][0] + rh[nd][p][1] * rh[nd][q][1] +
                  rh[nd][p][2] * rh[nd][q][2];
        c = fminf(fmaxf(c, -1.0f + 1e-6f), 1.0f - 1e-6f);
        float c2 = 2.0f * c;
        float t0 = 1.0f, t1 = c;
        float acc;
        {
            float s = 1.0f + sx[nd][0][p] + sx[nd][0][q];
            float si = __fdividef(s, 1.0f + __expf(-s));
            acc = sat[0] * si;
        }
#pragma unroll
        for (int k = 1; k < 64; k++) {
            float z = t1;
            float s = z + sx[nd][k][p] + sx[nd][k][q];
            float si = __fdividef(s, 1.0f + __expf(-s));
            acc = fmaf(sat[k], si, acc);
            float tn = fmaf(c2, t1, -t0);
            t0 = t1; t1 = tn;
        }
        sl[nd][q][p] = acc;
        sl[nd][p][q - 1] = acc;
    }
    __syncthreads();

    if (t < 32) {
        int nd = t >> 4, q = t & 15;
        float m = -1e30f;
#pragma unroll
        for (int ps = 0; ps < 15; ps++) m = fmaxf(m, sl[nd][q][ps]);
        float z = 0.0f;
#pragma unroll
        for (int ps = 0; ps < 15; ps++) z += __expf(sl[nd][q][ps] - m);
        mq[nd][q] = m;
        zi[nd][q] = __fdividef(1.0f, z);
    }
    __syncthreads();

    if (t < 32) {
        int nd = t >> 4, p = t & 15;
        float w = 0.0f;
#pragma unroll
        for (int q = 0; q < 16; q++) {
            if (q == p) continue;
            int ps = (p < q) ? p : p - 1;
            w += __expf(sl[nd][q][ps] - mq[nd][q]) * zi[nd][q];
        }
        wp[nd][p] = w;
    }
    __syncthreads();

    if (t < 128) {
        int nd = t >> 6, k = t & 63;
        float acc = 0.0f;
#pragma unroll
        for (int p = 0; p < 16; p++) acc = fmaf(wp[nd][p], sx[nd][k][p], acc);
        xn[(n0 + nd) * 64 + k] = acc;
    }
}

// ---------------- SGEMM: C[M,N] = A[M,K] @ B[N,K]^T + bias ---------------------
// EPI 1: silu(+bias)
// EPI 4: fused dual projection with K-split: grid (2, MB, 2)
template <int EPI>
__global__ __launch_bounds__(128)
void gemm64(const float* __restrict__ A,
            const float* __restrict__ B,
            float* __restrict__ C,
            int M, int N, int K, int lda, int ldb,
            const float* __restrict__ bias,
            const float* __restrict__ bias2) {
    __shared__ float As[32][64];
    __shared__ float Bs[32][64];
    int t = threadIdx.x;
    int n0 = blockIdx.x * 64;
    int m0 = blockIdx.y * 64;
    if (EPI == 4) {
        int z = blockIdx.z;
        int wsel = blockIdx.x;
        B = B + (size_t)wsel * 64 * 1024 + z * 512;
        bias = (z == 0) ? (bias + wsel * 64) : bias2;
        C = C + (size_t)(z * 2 + wsel) * (N_NODES * 64);
        A = A + z * 512;
        n0 = 0;
    }
    int r = t & 63;
    int kb = (t >> 6) * 16;
    int rg8 = (t >> 4) * 8;
    int cg4 = (t & 15) * 4;

    uint64_t acc2[4][4];
#pragma unroll
    for (int i = 0; i < 4; i++)
#pragma unroll
        for (int j = 0; j < 4; j++) acc2[i][j] = 0ull;

    int rowA = m0 + r;
    bool okA = rowA < M;
    const float* Ap = A + (size_t)(okA ? rowA : (M - 1)) * lda + kb;
    const float* Bp = B + (size_t)(n0 + r) * ldb + kb;

    for (int k0 = 0; k0 < K; k0 += 32) {
        float4 av[4], bv[4];
#pragma unroll
        for (int i = 0; i < 4; i++) {
            av[i] = okA ? *(const float4*)(Ap + k0 + i * 4)
                        : make_float4(0.f, 0.f, 0.f, 0.f);
            bv[i] = *(const float4*)(Bp + k0 + i * 4);
        }
        __syncthreads();
#pragma unroll
        for (int i = 0; i < 4; i++) {
            As[kb + i * 4 + 0][r] = av[i].x;
            As[kb + i * 4 + 1][r] = av[i].y;
            As[kb + i * 4 + 2][r] = av[i].z;
            As[kb + i * 4 + 3][r] = av[i].w;
            Bs[kb + i * 4 + 0][r] = bv[i].x;
            Bs[kb + i * 4 + 1][r] = bv[i].y;
            Bs[kb + i * 4 + 2][r] = bv[i].z;
            Bs[kb + i * 4 + 3][r] = bv[i].w;
        }
        __syncthreads();
#pragma unroll 8
        for (int kk = 0; kk < 32; kk++) {
            float4 a0 = *(const float4*)&As[kk][rg8];
            float4 a1 = *(const float4*)&As[kk][rg8 + 4];
            float4 b = *(const float4*)&Bs[kk][cg4];
            uint64_t ap[4] = {pk2(a0.x, a0.y), pk2(a0.z, a0.w),
                              pk2(a1.x, a1.y), pk2(a1.z, a1.w)};
            uint64_t bd[4] = {pk2(b.x, b.x), pk2(b.y, b.y),
                              pk2(b.z, b.z), pk2(b.w, b.w)};
#pragma unroll
            for (int i = 0; i < 4; i++)
#pragma unroll
                for (int j = 0; j < 4; j++)
                    ffma2(acc2[i][j], ap[i], bd[j]);
        }
    }
    __syncthreads();

    float4 b4 = *(const float4*)&bias[n0 + cg4];
    float bb[4] = {b4.x, b4.y, b4.z, b4.w};
#pragma unroll
    for (int i = 0; i < 4; i++) {
        float v0[4], v1[4];
#pragma unroll
        for (int j = 0; j < 4; j++) {
            float lo, hi;
            upk2(lo, hi, acc2[i][j]);
            lo += bb[j];
            hi += bb[j];
            if (EPI == 1) {
                lo = __fdividef(lo, 1.0f + __expf(-lo));
                hi = __fdividef(hi, 1.0f + __expf(-hi));
            }
            v0[j] = lo;
            v1[j] = hi;
        }
        int m = m0 + rg8 + 2 * i;
        if (m < M)
            *(float4*)&C[(size_t)m * N + n0 + cg4] =
                make_float4(v0[0], v0[1], v0[2], v0[3]);
        if (m + 1 < M)
            *(float4*)&C[(size_t)(m + 1) * N + n0 + cg4] =
                make_float4(v1[0], v1[1], v1[2], v1[3]);
    }
}

// ---------------- combine K-split projection partials ----------------
__global__ void projadd_kernel(const float* __restrict__ sp,
                               float* __restrict__ xj,
                               float* __restrict__ xi) {
    int i = blockIdx.x * 256 + threadIdx.x;
    if (i < N_NODES * 16) {
        const float4* s0 = (const float4*)sp;
        float4 a = s0[i];
        float4 b = s0[2 * N_NODES * 16 + i];
        ((float4*)xj)[i] = make_float4(a.x + b.x, a.y + b.y, a.z + b.z, a.w + b.w);
        float4 c = s0[N_NODES * 16 + i];
        float4 d = s0[3 * N_NODES * 16 + i];
        ((float4*)xi)[i] = make_float4(c.x + d.x, c.y + d.y, c.z + d.z, c.w + d.w);
    }
}

// ---------------- head ----------------
__global__ void colsum1_kernel(const float* __restrict__ h,
                               float* __restrict__ hpart) {
    int f = blockIdx.y * 256 + threadIdx.x;
    int n0 = blockIdx.x * 100;
    float acc = 0.0f;
    for (int n = n0; n < n0 + 100; n++) acc += h[(size_t)n * D_FF + f];
    hpart[blockIdx.x * D_FF + f] = acc;
}

__global__ void final_kernel(const float* __restrict__ hpart,
                             const float* __restrict__ wfc2,
                             const float* __restrict__ b2l2,
                             const float* __restrict__ Wfc,
                             const float* __restrict__ bfc,
                             float* __restrict__ out) {
    __shared__ float red[256];
    int t = threadIdx.x;
    float acc = 0.0f;
    for (int f = t; f < D_FF; f += 256) {
        float hs = 0.0f;
        for (int b = 0; b < 60; b++) hs += hpart[b * D_FF + f];
        acc = fmaf(hs, wfc2[f], acc);
    }
    acc *= (1.0f / (float)N_NODES);
    acc = fmaf(b2l2[t], Wfc[t], acc);
    red[t] = acc;
    __syncthreads();
    for (int s = 128; s > 0; s >>= 1) {
        if (t < s) red[t] += red[t + s];
        __syncthreads();
    }
    if (t == 0) out[0] = red[0] + bfc[0];
}

// ---------------- launcher ----------------
extern "C" void kernel_launch(void* const* d_in, const int* in_sizes, int n_in,
                              void* d_out, int out_size) {
    const float* r     = (const float*)d_in[0];
    const int*   an    = (const int*)d_in[1];
    const int*   src   = (const int*)d_in[2];
    const float* emb   = (const float*)d_in[6];
    const float* Wsrc  = (const float*)d_in[7];
    const float* bsrc  = (const float*)d_in[8];
    const float* Wdst  = (const float*)d_in[9];
    const float* bdst  = (const float*)d_in[10];
    const float* Wedge = (const float*)d_in[11];
    const float* bedge = (const float*)d_in[12];
    const float* attn  = (const float*)d_in[13];
    const float* W1    = (const float*)d_in[14];
    const float* b1    = (const float*)d_in[15];
    const float* W2    = (const float*)d_in[16];
    const float* b2    = (const float*)d_in[17];
    const float* Wfc   = (const float*)d_in[18];
    const float* bfc   = (const float*)d_in[19];
    float* out = (float*)d_out;

    float *xj, *xi, *xjsplit, *xij, *xn, *h, *wc, *es, *ed, *bx;
    float *hpart, *wfc2, *zeros;
    cudaGetSymbolAddress((void**)&xj,   g_xj);
    cudaGetSymbolAddress((void**)&xi,   g_xi);
    cudaGetSymbolAddress((void**)&xjsplit, g_xjsplit);
    cudaGetSymbolAddress((void**)&xij,  g_xij);
    cudaGetSymbolAddress((void**)&xn,   g_xn);
    cudaGetSymbolAddress((void**)&h,    g_h);
    cudaGetSymbolAddress((void**)&wc,   g_wc);
    cudaGetSymbolAddress((void**)&es,   g_embsrc);
    cudaGetSymbolAddress((void**)&ed,   g_embdst);
    cudaGetSymbolAddress((void**)&bx,   g_bx);
    cudaGetSymbolAddress((void**)&hpart, g_hpart);
    cudaGetSymbolAddress((void**)&wfc2, g_wfc2);
    cudaGetSymbolAddress((void**)&zeros, g_zeros);

    cudaFuncSetAttribute(edge_kernel,
                         cudaFuncAttributeMaxDynamicSharedMemorySize,
                         EDGE_SMEM_BYTES);

    // ---------- precompute ----------
    species_kernel<<<N_SPEC, 128>>>(emb, Wsrc, bsrc, Wdst, bdst, es, ed);
    wc_kernel<<<dim3(8, 4), 256>>>(Wsrc, Wdst, W2, wc);
    biasfold_kernel<<<4, 64>>>(Wsrc, Wdst, bsrc, bdst, b2, bx);
    wfc2_kernel<<<4, 256>>>(W2 + 2 * D_MODEL * D_FF, Wfc, wfc2);
    gather_kernel<<<N_NODES, 64>>>(an, es, ed, xj, xi);

    const int MB_NODE = (N_NODES + 63) / 64;   // 94

    // ---------- layers ----------
    for (int l = 0; l < N_LAYERS; l++) {
        edge_kernel<<<444, 256, EDGE_SMEM_BYTES>>>(
            r, src, Wedge + l * 64 * 256, bedge + l * 64, xj, xi, xij);
        triplet_kernel<<<N_NODES / 2, 256>>>(xij, r, attn + l * 64, xn);
        gemm64<1><<<dim3(16, MB_NODE), 128>>>(
            xn, W1 + l * D_FF * 64, h, N_NODES, D_FF, 64, 64, 64,
            b1 + l * D_FF, nullptr);
        if (l < 2) {
            gemm64<4><<<dim3(2, MB_NODE, 2), 128>>>(
                h, wc + (size_t)(2 * l) * 64 * D_FF, xjsplit,
                N_NODES, 64, 512, 1024, 1024,
                bx + 2 * l * 64, zeros);
            projadd_kernel<<<(N_NODES * 16 + 255) / 256, 256>>>(xjsplit, xj, xi);
        }
    }

    // ---------- head ----------
    colsum1_kernel<<<dim3(60, 4), 256>>>(h, hpart);
    final_kernel<<<1, 256>>>(hpart, wfc2, b2 + 2 * D_MODEL, Wfc, bfc, out);
}

// round 15
// speedup vs baseline: 1.1664x; 1.0256x over previous
#include <cuda_runtime.h>
#include <math.h>
#include <stdint.h>

#define N_NODES 6000
#define DEG 16
#define N_EDGES 96000
#define D_MODEL 256
#define D_MSG 64
#define D_FF 1024
#define N_LAYERS 3
#define RBF_BINS 256
#define WIN 32
#define N_SPEC 108

// ---------------- scratch (static device memory; no allocation) ----------------
__device__ float g_xj[N_NODES * D_MSG];
__device__ float g_xi[N_NODES * D_MSG];
__device__ float g_xjsplit[4 * N_NODES * D_MSG];
__device__ float g_xij[N_EDGES * D_MSG];
__device__ float g_xn[N_NODES * D_MSG];
__device__ float g_h[N_NODES * D_FF];
__device__ float g_wc[4 * D_MSG * D_FF];
__device__ float g_embsrc[112 * D_MSG];
__device__ float g_embdst[112 * D_MSG];
__device__ float g_bx[4 * D_MSG];
__device__ float g_hpart[60 * D_FF];
__device__ float g_wfc2p[8 * D_FF];
__device__ float g_zeros[D_FF];            // zero-initialized

// ---------------- packed f32x2 helpers (sm_10x) ----------------
__device__ __forceinline__ uint64_t pk2(float lo, float hi) {
    uint64_t r;
    asm("mov.b64 %0, {%1, %2};" : "=l"(r) : "f"(lo), "f"(hi));
    return r;
}
__device__ __forceinline__ void upk2(float& lo, float& hi, uint64_t v) {
    asm("mov.b64 {%0, %1}, %2;" : "=f"(lo), "=f"(hi) : "l"(v));
}
__device__ __forceinline__ void ffma2(uint64_t& d, uint64_t a, uint64_t b) {
    asm("fma.rn.f32x2 %0, %1, %2, %0;" : "+l"(d) : "l"(a), "l"(b));
}

// ---------------- species projections: es/ed = emb @ W0^T + b ----------------
__global__ void species_kernel(const float* __restrict__ emb,
                               const float* __restrict__ Wsrc,
                               const float* __restrict__ bsrc,
                               const float* __restrict__ Wdst,
                               const float* __restrict__ bdst,
                               float* __restrict__ es,
                               float* __restrict__ ed) {
    __shared__ float se[256];
    int s = blockIdx.x;
    int t = threadIdx.x;
    se[t] = emb[s * 256 + t];
    se[t + 128] = emb[s * 256 + t + 128];
    __syncthreads();
    int c = t & 63;
    bool isdst = t >= 64;
    const float* W = (isdst ? Wdst : Wsrc) + c * 256;
    float acc = isdst ? bdst[c] : bsrc[c];
#pragma unroll 16
    for (int k = 0; k < 256; k += 4) {
        float4 w = *(const float4*)(W + k);
        acc = fmaf(se[k + 0], w.x, acc);
        acc = fmaf(se[k + 1], w.y, acc);
        acc = fmaf(se[k + 2], w.z, acc);
        acc = fmaf(se[k + 3], w.w, acc);
    }
    (isdst ? ed : es)[s * 64 + c] = acc;
}

// ---------------- fused weight precompute: wc[s] = W[s] @ W2[l(s)] ------------
__global__ void wc_kernel(const float* __restrict__ Wsrc,
                          const float* __restrict__ Wdst,
                          const float* __restrict__ W2,
                          float* __restrict__ wc) {
    __shared__ float sW[64 * 32];
    __shared__ float sW2[32 * 128];
    int s = blockIdx.y;
    int l = 1 + (s >> 1);
    const float* W = ((s & 1) ? Wdst : Wsrc) + (size_t)l * 64 * 256;
    const float* W2l = W2 + (size_t)(s >> 1) * 256 * 1024;
    int f0 = blockIdx.x * 128;
    int t = threadIdx.x;
    int tf = t & 31;
    int tcg = t >> 5;
    float acc[8][4];
#pragma unroll
    for (int i = 0; i < 8; i++)
#pragma unroll
        for (int j = 0; j < 4; j++) acc[i][j] = 0.0f;

    for (int k0 = 0; k0 < 256; k0 += 32) {
        __syncthreads();
        for (int i = t; i < 64 * 32; i += 256) {
            int c = i >> 5, k = i & 31;
            sW[c * 32 + k] = W[c * 256 + k0 + k];
        }
        for (int i = t; i < 32 * 128; i += 256) {
            int k = i >> 7, f = i & 127;
            sW2[k * 128 + f] = W2l[(size_t)(k0 + k) * 1024 + f0 + f];
        }
        __syncthreads();
#pragma unroll 8
        for (int k = 0; k < 32; k++) {
            float4 w2 = *(const float4*)&sW2[k * 128 + tf * 4];
#pragma unroll
            for (int i = 0; i < 8; i++) {
                float a = sW[(tcg * 8 + i) * 32 + k];
                acc[i][0] = fmaf(a, w2.x, acc[i][0]);
                acc[i][1] = fmaf(a, w2.y, acc[i][1]);
                acc[i][2] = fmaf(a, w2.z, acc[i][2]);
                acc[i][3] = fmaf(a, w2.w, acc[i][3]);
            }
        }
    }
#pragma unroll
    for (int i = 0; i < 8; i++)
        *(float4*)&wc[(size_t)s * 64 * 1024 + (size_t)(tcg * 8 + i) * 1024 +
                      f0 + tf * 4] =
            make_float4(acc[i][0], acc[i][1], acc[i][2], acc[i][3]);
}

// ---------------- fused bias (k-split + smem reduce) ----------------
__global__ void biasfold_kernel(const float* __restrict__ Wsrc,
                                const float* __restrict__ Wdst,
                                const float* __restrict__ bsrc,
                                const float* __restrict__ bdst,
                                const float* __restrict__ b2,
                                float* __restrict__ bx) {
    __shared__ float red[4][64];
    int which = blockIdx.x;
    int l = 1 + (which >> 1);
    bool isdst = which & 1;
    const float* W = (isdst ? Wdst : Wsrc) + (size_t)l * D_MSG * D_MODEL;
    const float* bb = (isdst ? bdst : bsrc) + (size_t)l * D_MSG;
    const float* b2p = b2 + (size_t)(l - 1) * D_MODEL;
    int t = threadIdx.x;
    int c = t & 63;
    int part = t >> 6;                 // 0..3, k in [part*64, part*64+64)
    float acc = 0.0f;
#pragma unroll 16
    for (int k = part * 64; k < part * 64 + 64; k++)
        acc = fmaf(W[c * D_MODEL + k], b2p[k], acc);
    red[part][c] = acc;
    __syncthreads();
    if (t < 64)
        bx[which * D_MSG + t] =
            bb[t] + red[0][t] + red[1][t] + red[2][t] + red[3][t];
}

// ---------------- wfc2 partials (k-split, coalesced) ----------------
__global__ void wfc2_kernel(const float* __restrict__ W2l2,
                            const float* __restrict__ Wfc,
                            float* __restrict__ wfc2p) {
    int f = blockIdx.x * 256 + threadIdx.x;
    int kc = blockIdx.y;               // 0..7, k in [kc*32, kc*32+32)
    float acc = 0.0f;
#pragma unroll 8
    for (int k = kc * 32; k < kc * 32 + 32; k++)
        acc = fmaf(W2l2[(size_t)k * D_FF + f], Wfc[k], acc);
    wfc2p[kc * D_FF + f] = acc;
}

// ---------------- layer-0 projection gather (4 nodes/block, float4) ----------
__global__ void gather_kernel(const int* __restrict__ an,
                              const float* __restrict__ es,
                              const float* __restrict__ ed,
                              float* __restrict__ xj,
                              float* __restrict__ xi) {
    int t = threadIdx.x;
    int node = blockIdx.x * 4 + (t >> 6);
    int c4 = (t & 15);                 // float4 within row: 64/4=16
    bool half = (t >> 4) & 1;          // which of xj/xi... no, need both
    // each node-row has 16 float4; 64 threads per node: 16 for xj, 16 for xi x2? 
    // simpler: 64 threads/node: t4 = t&63; first 32 -> xj halves? 
    int a = an[node];
    int lane = t & 63;
    if (lane < 16) {
        ((float4*)&xj[node * 64])[lane] = ((const float4*)&es[a * 64])[lane];
    } else if (lane < 32) {
        ((float4*)&xi[node * 64])[lane - 16] =
            ((const float4*)&ed[a * 64])[lane - 16];
    }
    (void)c4; (void)half;
}

// ---------------- fused windowed-RBF edge kernel (f32x2 dot) ------------------
#define EDGE_WPITCH 68
#define EDGE_SMEM_BYTES (256 * EDGE_WPITCH * 4 + 16 * WIN * 4 + 16 * 4 * 3)

__global__ void edge_kernel(const float* __restrict__ r,
                            const int* __restrict__ src,
                            const float* __restrict__ We,
                            const float* __restrict__ bedge,
                            const float* __restrict__ xj,
                            const float* __restrict__ xi,
                            float* __restrict__ xij) {
    extern __shared__ float sm[];
    float* sWt = sm;
    float* sy = sm + 256 * EDGE_WPITCH;
    int* sb0 = (int*)(sy + 16 * WIN);
    int* ssrc = sb0 + 16;
    float* sd = (float*)(ssrc + 16);

    int t = threadIdx.x;
    for (int idx = t; idx < 64 * 256; idx += 256) {
        int ch = idx >> 8, b = idx & 255;
        sWt[b * EDGE_WPITCH + ch] = We[idx];
    }
    int e_sub = t >> 4;
    int chv = t & 15;
    float4 bed = *(const float4*)&bedge[chv * 4];
    const float inv_step = 255.0f / 8.0f;
    const float step = 8.0f / 255.0f;
    const float gamma = inv_step;

    for (int g = blockIdx.x; g < N_NODES; g += gridDim.x) {
        __syncthreads();
        if (t < 16) {
            int e = g * 16 + t;
            float rx = r[e * 3 + 0], ry = r[e * 3 + 1], rz = r[e * 3 + 2];
            float d = sqrtf(rx * rx + ry * ry + rz * rz);
            int cb = (int)(d * inv_step + 0.5f);
            int b0 = cb - WIN / 2;
            b0 = b0 < 0 ? 0 : (b0 > 256 - WIN ? 256 - WIN : b0);
            sb0[t] = b0;
            sd[t] = d;
            ssrc[t] = src[e];
        }
        __syncthreads();
        {
            float d = sd[e_sub];
            int b0 = sb0[e_sub];
            int jb = chv * 2;
#pragma unroll
            for (int i = 0; i < 2; i++) {
                float tt = d - (float)(b0 + jb + i) * step;
                sy[e_sub * WIN + jb + i] = __expf(-gamma * tt * tt);
            }
        }
        __syncthreads();
        {
            int b0 = sb0[e_sub];
            const float* wp = sWt + (size_t)b0 * EDGE_WPITCH + chv * 4;
            const float* yp = sy + e_sub * WIN;
            uint64_t a0 = pk2(bed.x, bed.y);
            uint64_t a1 = pk2(bed.z, bed.w);
#pragma unroll 16
            for (int j = 0; j < WIN; j++) {
                float yv = yp[j];
                uint64_t yd = pk2(yv, yv);
                float4 w = *(const float4*)(wp + (size_t)j * EDGE_WPITCH);
                ffma2(a0, yd, pk2(w.x, w.y));
                ffma2(a1, yd, pk2(w.z, w.w));
            }
            int sidx = ssrc[e_sub];
            float4 aj = *(const float4*)&xj[sidx * 64 + chv * 4];
            float4 ai = *(const float4*)&xi[g * 64 + chv * 4];
            float o0, o1, o2, o3;
            upk2(o0, o1, a0);
            upk2(o2, o3, a1);
            float4 res = make_float4(o0 + aj.x + ai.x, o1 + aj.y + ai.y,
                                     o2 + aj.z + ai.z, o3 + aj.w + ai.w);
            *(float4*)&xij[(size_t)(g * 16 + e_sub) * 64 + chv * 4] = res;
        }
    }
}

// ---------------- triplet attention: 2 nodes per 256-thread block -------------
__global__ void triplet_kernel(const float* __restrict__ xij,
                               const float* __restrict__ r,
                               const float* __restrict__ attn,
                               float* __restrict__ xn) {
    __shared__ float sx[2][64][17];
    __shared__ float rh[2][16][3];
    __shared__ float sat[64];
    __shared__ float sl[2][16][16];
    __shared__ float mq[2][16], zi[2][16], wp[2][16];

    int n0 = blockIdx.x * 2;
    int t = threadIdx.x;
    const float* xb = xij + (size_t)n0 * 16 * 64;

    for (int idx = t; idx < 2048; idx += 256) {
        int nd = idx >> 10, p = (idx >> 6) & 15, k = idx & 63;
        sx[nd][k][p] = xb[idx];
    }
    if (t < 32) {
        int e = n0 * 16 + t;
        float rx = r[e * 3 + 0], ry = r[e * 3 + 1], rz = r[e * 3 + 2];
        float inv = rsqrtf(rx * rx + ry * ry + rz * rz);
        int nd = t >> 4, le = t & 15;
        rh[nd][le][0] = rx * inv;
        rh[nd][le][1] = ry * inv;
        rh[nd][le][2] = rz * inv;
    }
    if (t < 64) sat[t] = attn[t];
    __syncthreads();

    if (t < 240) {
        int nd = t / 120;
        int tt = t - nd * 120;
        int q = (int)((1.0f + sqrtf(8.0f * (float)tt + 1.0f)) * 0.5f);
        if (q * (q - 1) / 2 > tt) q--;
        else if (q * (q + 1) / 2 <= tt) q++;
        int p = tt - q * (q - 1) / 2;

        float c = rh[nd][p][0] * rh[nd][q][0] + rh[nd][p][1] * rh[nd][q][1] +
                  rh[nd][p][2] * rh[nd][q][2];
        c = fminf(fmaxf(c, -1.0f + 1e-6f), 1.0f - 1e-6f);
        float c2 = 2.0f * c;
        float t0 = 1.0f, t1 = c;
        float acc;
        {
            float s = 1.0f + sx[nd][0][p] + sx[nd][0][q];
            float si = __fdividef(s, 1.0f + __expf(-s));
            acc = sat[0] * si;
        }
#pragma unroll
        for (int k = 1; k < 64; k++) {
            float z = t1;
            float s = z + sx[nd][k][p] + sx[nd][k][q];
            float si = __fdividef(s, 1.0f + __expf(-s));
            acc = fmaf(sat[k], si, acc);
            float tn = fmaf(c2, t1, -t0);
            t0 = t1; t1 = tn;
        }
        sl[nd][q][p] = acc;
        sl[nd][p][q - 1] = acc;
    }
    __syncthreads();

    if (t < 32) {
        int nd = t >> 4, q = t & 15;
        float m = -1e30f;
#pragma unroll
        for (int ps = 0; ps < 15; ps++) m = fmaxf(m, sl[nd][q][ps]);
        float z = 0.0f;
#pragma unroll
        for (int ps = 0; ps < 15; ps++) z += __expf(sl[nd][q][ps] - m);
        mq[nd][q] = m;
        zi[nd][q] = __fdividef(1.0f, z);
    }
    __syncthreads();

    if (t < 32) {
        int nd = t >> 4, p = t & 15;
        float w = 0.0f;
#pragma unroll
        for (int q = 0; q < 16; q++) {
            if (q == p) continue;
            int ps = (p < q) ? p : p - 1;
            w += __expf(sl[nd][q][ps] - mq[nd][q]) * zi[nd][q];
        }
        wp[nd][p] = w;
    }
    __syncthreads();

    if (t < 128) {
        int nd = t >> 6, k = t & 63;
        float acc = 0.0f;
#pragma unroll
        for (int p = 0; p < 16; p++) acc = fmaf(wp[nd][p], sx[nd][k][p], acc);
        xn[(n0 + nd) * 64 + k] = acc;
    }
}

// ---------------- SGEMM: C[M,N] = A[M,K] @ B[N,K]^T + bias ---------------------
// EPI 1: silu(+bias)
// EPI 4: fused dual projection with K-split: grid (2, MB, 2)
template <int EPI>
__global__ __launch_bounds__(128)
void gemm64(const float* __restrict__ A,
            const float* __restrict__ B,
            float* __restrict__ C,
            int M, int N, int K, int lda, int ldb,
            const float* __restrict__ bias,
            const float* __restrict__ bias2) {
    __shared__ float As[32][64];
    __shared__ float Bs[32][64];
    int t = threadIdx.x;
    int n0 = blockIdx.x * 64;
    int m0 = blockIdx.y * 64;
    if (EPI == 4) {
        int z = blockIdx.z;
        int wsel = blockIdx.x;
        B = B + (size_t)wsel * 64 * 1024 + z * 512;
        bias = (z == 0) ? (bias + wsel * 64) : bias2;
        C = C + (size_t)(z * 2 + wsel) * (N_NODES * 64);
        A = A + z * 512;
        n0 = 0;
    }
    int r = t & 63;
    int kb = (t >> 6) * 16;
    int rg8 = (t >> 4) * 8;
    int cg4 = (t & 15) * 4;

    uint64_t acc2[4][4];
#pragma unroll
    for (int i = 0; i < 4; i++)
#pragma unroll
        for (int j = 0; j < 4; j++) acc2[i][j] = 0ull;

    int rowA = m0 + r;
    bool okA = rowA < M;
    const float* Ap = A + (size_t)(okA ? rowA : (M - 1)) * lda + kb;
    const float* Bp = B + (size_t)(n0 + r) * ldb + kb;

    for (int k0 = 0; k0 < K; k0 += 32) {
        float4 av[4], bv[4];
#pragma unroll
        for (int i = 0; i < 4; i++) {
            av[i] = okA ? *(const float4*)(Ap + k0 + i * 4)
                        : make_float4(0.f, 0.f, 0.f, 0.f);
            bv[i] = *(const float4*)(Bp + k0 + i * 4);
        }
        __syncthreads();
#pragma unroll
        for (int i = 0; i < 4; i++) {
            As[kb + i * 4 + 0][r] = av[i].x;
            As[kb + i * 4 + 1][r] = av[i].y;
            As[kb + i * 4 + 2][r] = av[i].z;
            As[kb + i * 4 + 3][r] = av[i].w;
            Bs[kb + i * 4 + 0][r] = bv[i].x;
            Bs[kb + i * 4 + 1][r] = bv[i].y;
            Bs[kb + i * 4 + 2][r] = bv[i].z;
            Bs[kb + i * 4 + 3][r] = bv[i].w;
        }
        __syncthreads();
#pragma unroll 8
        for (int kk = 0; kk < 32; kk++) {
            float4 a0 = *(const float4*)&As[kk][rg8];
            float4 a1 = *(const float4*)&As[kk][rg8 + 4];
            float4 b = *(const float4*)&Bs[kk][cg4];
            uint64_t ap[4] = {pk2(a0.x, a0.y), pk2(a0.z, a0.w),
                              pk2(a1.x, a1.y), pk2(a1.z, a1.w)};
            uint64_t bd[4] = {pk2(b.x, b.x), pk2(b.y, b.y),
                              pk2(b.z, b.z), pk2(b.w, b.w)};
#pragma unroll
            for (int i = 0; i < 4; i++)
#pragma unroll
                for (int j = 0; j < 4; j++)
                    ffma2(acc2[i][j], ap[i], bd[j]);
        }
    }
    __syncthreads();

    float4 b4 = *(const float4*)&bias[n0 + cg4];
    float bb[4] = {b4.x, b4.y, b4.z, b4.w};
#pragma unroll
    for (int i = 0; i < 4; i++) {
        float v0[4], v1[4];
#pragma unroll
        for (int j = 0; j < 4; j++) {
            float lo, hi;
            upk2(lo, hi, acc2[i][j]);
            lo += bb[j];
            hi += bb[j];
            if (EPI == 1) {
                lo = __fdividef(lo, 1.0f + __expf(-lo));
                hi = __fdividef(hi, 1.0f + __expf(-hi));
            }
            v0[j] = lo;
            v1[j] = hi;
        }
        int m = m0 + rg8 + 2 * i;
        if (m < M)
            *(float4*)&C[(size_t)m * N + n0 + cg4] =
                make_float4(v0[0], v0[1], v0[2], v0[3]);
        if (m + 1 < M)
            *(float4*)&C[(size_t)(m + 1) * N + n0 + cg4] =
                make_float4(v1[0], v1[1], v1[2], v1[3]);
    }
}

// ---------------- combine K-split projection partials ----------------
__global__ void projadd_kernel(const float* __restrict__ sp,
                               float* __restrict__ xj,
                               float* __restrict__ xi) {
    int i = blockIdx.x * 256 + threadIdx.x;
    if (i < N_NODES * 16) {
        const float4* s0 = (const float4*)sp;
        float4 a = s0[i];
        float4 b = s0[2 * N_NODES * 16 + i];
        ((float4*)xj)[i] = make_float4(a.x + b.x, a.y + b.y, a.z + b.z, a.w + b.w);
        float4 c = s0[N_NODES * 16 + i];
        float4 d = s0[3 * N_NODES * 16 + i];
        ((float4*)xi)[i] = make_float4(c.x + d.x, c.y + d.y, c.z + d.z, c.w + d.w);
    }
}

// ---------------- head ----------------
__global__ void colsum1_kernel(const float* __restrict__ h,
                               float* __restrict__ hpart) {
    int f = blockIdx.y * 256 + threadIdx.x;
    int n0 = blockIdx.x * 100;
    float acc = 0.0f;
    for (int n = n0; n < n0 + 100; n++) acc += h[(size_t)n * D_FF + f];
    hpart[blockIdx.x * D_FF + f] = acc;
}

__global__ void final_kernel(const float* __restrict__ hpart,
                             const float* __restrict__ wfc2p,
                             const float* __restrict__ b2l2,
                             const float* __restrict__ Wfc,
                             const float* __restrict__ bfc,
                             float* __restrict__ out) {
    __shared__ float red[256];
    int t = threadIdx.x;
    float acc = 0.0f;
    for (int f = t; f < D_FF; f += 256) {
        float hs = 0.0f;
        for (int b = 0; b < 60; b++) hs += hpart[b * D_FF + f];
        float w = 0.0f;
#pragma unroll
        for (int kc = 0; kc < 8; kc++) w += wfc2p[kc * D_FF + f];
        acc = fmaf(hs, w, acc);
    }
    acc *= (1.0f / (float)N_NODES);
    acc = fmaf(b2l2[t], Wfc[t], acc);
    red[t] = acc;
    __syncthreads();
    for (int s = 128; s > 0; s >>= 1) {
        if (t < s) red[t] += red[t + s];
        __syncthreads();
    }
    if (t == 0) out[0] = red[0] + bfc[0];
}

// ---------------- launcher ----------------
extern "C" void kernel_launch(void* const* d_in, const int* in_sizes, int n_in,
                              void* d_out, int out_size) {
    const float* r     = (const float*)d_in[0];
    const int*   an    = (const int*)d_in[1];
    const int*   src   = (const int*)d_in[2];
    const float* emb   = (const float*)d_in[6];
    const float* Wsrc  = (const float*)d_in[7];
    const float* bsrc  = (const float*)d_in[8];
    const float* Wdst  = (const float*)d_in[9];
    const float* bdst  = (const float*)d_in[10];
    const float* Wedge = (const float*)d_in[11];
    const float* bedge = (const float*)d_in[12];
    const float* attn  = (const float*)d_in[13];
    const float* W1    = (const float*)d_in[14];
    const float* b1    = (const float*)d_in[15];
    const float* W2    = (const float*)d_in[16];
    const float* b2    = (const float*)d_in[17];
    const float* Wfc   = (const float*)d_in[18];
    const float* bfc   = (const float*)d_in[19];
    float* out = (float*)d_out;

    float *xj, *xi, *xjsplit, *xij, *xn, *h, *wc, *es, *ed, *bx;
    float *hpart, *wfc2p, *zeros;
    cudaGetSymbolAddress((void**)&xj,   g_xj);
    cudaGetSymbolAddress((void**)&xi,   g_xi);
    cudaGetSymbolAddress((void**)&xjsplit, g_xjsplit);
    cudaGetSymbolAddress((void**)&xij,  g_xij);
    cudaGetSymbolAddress((void**)&xn,   g_xn);
    cudaGetSymbolAddress((void**)&h,    g_h);
    cudaGetSymbolAddress((void**)&wc,   g_wc);
    cudaGetSymbolAddress((void**)&es,   g_embsrc);
    cudaGetSymbolAddress((void**)&ed,   g_embdst);
    cudaGetSymbolAddress((void**)&bx,   g_bx);
    cudaGetSymbolAddress((void**)&hpart, g_hpart);
    cudaGetSymbolAddress((void**)&wfc2p, g_wfc2p);
    cudaGetSymbolAddress((void**)&zeros, g_zeros);

    cudaFuncSetAttribute(edge_kernel,
                         cudaFuncAttributeMaxDynamicSharedMemorySize,
                         EDGE_SMEM_BYTES);

    // ---------- precompute ----------
    species_kernel<<<N_SPEC, 128>>>(emb, Wsrc, bsrc, Wdst, bdst, es, ed);
    wc_kernel<<<dim3(8, 4), 256>>>(Wsrc, Wdst, W2, wc);
    biasfold_kernel<<<4, 256>>>(Wsrc, Wdst, bsrc, bdst, b2, bx);
    wfc2_kernel<<<dim3(4, 8), 256>>>(W2 + 2 * D_MODEL * D_FF, Wfc, wfc2p);
    gather_kernel<<<N_NODES / 4, 256>>>(an, es, ed, xj, xi);

    const int MB_NODE = (N_NODES + 63) / 64;   // 94

    // ---------- layers ----------
    for (int l = 0; l < N_LAYERS; l++) {
        edge_kernel<<<444, 256, EDGE_SMEM_BYTES>>>(
            r, src, Wedge + l * 64 * 256, bedge + l * 64, xj, xi, xij);
        triplet_kernel<<<N_NODES / 2, 256>>>(xij, r, attn + l * 64, xn);
        gemm64<1><<<dim3(16, MB_NODE), 128>>>(
            xn, W1 + l * D_FF * 64, h, N_NODES, D_FF, 64, 64, 64,
            b1 + l * D_FF, nullptr);
        if (l < 2) {
            gemm64<4><<<dim3(2, MB_NODE, 2), 128>>>(
                h, wc + (size_t)(2 * l) * 64 * D_FF, xjsplit,
                N_NODES, 64, 512, 1024, 1024,
                bx + 2 * l * 64, zeros);
            projadd_kernel<<<(N_NODES * 16 + 255) / 256, 256>>>(xjsplit, xj, xi);
        }
    }

    // ---------- head ----------
    colsum1_kernel<<<dim3(60, 4), 256>>>(h, hpart);
    final_kernel<<<1, 256>>>(hpart, wfc2p, b2 + 2 * D_MODEL, Wfc, bfc, out);
}